// round 6
// baseline (speedup 1.0000x reference)
#include <cuda_runtime.h>
#include <cuda_bf16.h>
#include <cstdint>

// Problem constants (fixed by the reference).
#define N_NODES 100000
#define N_EDGES 1600000
#define D_IN    256
#define D_HID   128
#define D_OUT   64

// NOTE: JAX default config has x64 disabled, so edge_index (requested int64)
// is materialized as int32. Previous round read it as int64 -> garbage
// indices -> illegal memory access. It is int32.

// ---------------------------------------------------------------------------
// Scratch (static __device__ globals — no allocation allowed in this harness)
// ---------------------------------------------------------------------------
__device__ __align__(16) float g_h   [(size_t)N_NODES * D_HID];  // x @ W1
__device__ __align__(16) float g_agg1[(size_t)N_NODES * D_HID];  // aggregated layer-1
__device__ __align__(16) float g_h2  [(size_t)N_NODES * D_OUT];  // relu(agg1+b1) @ W2
__device__ float g_dinv[N_NODES];
__device__ int   g_deg [N_NODES];

// ---------------------------------------------------------------------------
// Vector global reduction: red.global.add.v4.f32 (sm_90+)
// ---------------------------------------------------------------------------
__device__ __forceinline__ void red_add_v4(float* p, float a, float b, float c, float d) {
    asm volatile("red.global.add.v4.f32 [%0], {%1, %2, %3, %4};"
                 :: "l"(p), "f"(a), "f"(b), "f"(c), "f"(d) : "memory");
}

// ---------------------------------------------------------------------------
// Degree / normalization
// ---------------------------------------------------------------------------
__global__ void k_zero_deg() {
    int i = blockIdx.x * blockDim.x + threadIdx.x;
    if (i < N_NODES) g_deg[i] = 0;
}

__global__ void k_count_deg(const int* __restrict__ dst) {
    int e = blockIdx.x * blockDim.x + threadIdx.x;
    if (e < N_EDGES) atomicAdd(&g_deg[dst[e]], 1);
}

__global__ void k_dinv() {
    int i = blockIdx.x * blockDim.x + threadIdx.x;
    if (i < N_NODES) g_dinv[i] = rsqrtf(1.0f + (float)g_deg[i]);
}

// ---------------------------------------------------------------------------
// GEMM1: h = x @ W1   (M=100000, K=256, N=128)
// Epilogue: g_h = h ;  g_agg1 = h * dinv^2  (self-loop init, no memset needed)
// Classic 128x128x8 SIMT tile, 256 threads, 8x8 per thread.
// ---------------------------------------------------------------------------
__global__ __launch_bounds__(256) void k_gemm1(const float* __restrict__ x,
                                               const float* __restrict__ W1) {
    const int BM = 128, BK = 8;
    __shared__ __align__(16) float As[BK][BM];     // transposed A tile
    __shared__ __align__(16) float Bs[BK][128];

    int block_row = blockIdx.x * BM;
    int t  = threadIdx.x;
    int tx = t & 15;                 // 16 col groups * 8 cols
    int ty = t >> 4;                 // 16 row groups * 8 rows

    // A load map: one float4 per thread per iter (128 rows x 8 k)
    int arow = t >> 1;
    int acol = (t & 1) * 4;
    // B load map: one float4 per thread (8 rows x 128 cols)
    int brow = t >> 5;
    int bcol = (t & 31) * 4;

    float acc[8][8];
#pragma unroll
    for (int i = 0; i < 8; i++)
#pragma unroll
        for (int j = 0; j < 8; j++) acc[i][j] = 0.0f;

    for (int k0 = 0; k0 < D_IN; k0 += BK) {
        int gr = block_row + arow;
        float4 a = make_float4(0.f, 0.f, 0.f, 0.f);
        if (gr < N_NODES)
            a = *(const float4*)(x + (size_t)gr * D_IN + k0 + acol);
        As[acol + 0][arow] = a.x;
        As[acol + 1][arow] = a.y;
        As[acol + 2][arow] = a.z;
        As[acol + 3][arow] = a.w;

        *(float4*)&Bs[brow][bcol] =
            *(const float4*)(W1 + (size_t)(k0 + brow) * D_HID + bcol);
        __syncthreads();

#pragma unroll
        for (int k = 0; k < BK; k++) {
            float4 a0 = *(float4*)&As[k][ty * 8];
            float4 a1 = *(float4*)&As[k][ty * 8 + 4];
            float4 b0 = *(float4*)&Bs[k][tx * 8];
            float4 b1 = *(float4*)&Bs[k][tx * 8 + 4];
            float ra[8] = {a0.x, a0.y, a0.z, a0.w, a1.x, a1.y, a1.z, a1.w};
            float rb[8] = {b0.x, b0.y, b0.z, b0.w, b1.x, b1.y, b1.z, b1.w};
#pragma unroll
            for (int i = 0; i < 8; i++)
#pragma unroll
                for (int j = 0; j < 8; j++) acc[i][j] += ra[i] * rb[j];
        }
        __syncthreads();
    }

    // Epilogue: write h and agg1-init (self-loop term).
#pragma unroll
    for (int i = 0; i < 8; i++) {
        int row = block_row + ty * 8 + i;
        if (row >= N_NODES) break;
        float di  = g_dinv[row];
        float di2 = di * di;
        size_t base = (size_t)row * D_HID + tx * 8;
        float4 v0 = make_float4(acc[i][0], acc[i][1], acc[i][2], acc[i][3]);
        float4 v1 = make_float4(acc[i][4], acc[i][5], acc[i][6], acc[i][7]);
        *(float4*)(g_h + base)     = v0;
        *(float4*)(g_h + base + 4) = v1;
        float4 s0 = make_float4(v0.x * di2, v0.y * di2, v0.z * di2, v0.w * di2);
        float4 s1 = make_float4(v1.x * di2, v1.y * di2, v1.z * di2, v1.w * di2);
        *(float4*)(g_agg1 + base)     = s0;
        *(float4*)(g_agg1 + base + 4) = s1;
    }
}

// ---------------------------------------------------------------------------
// Scatter layer 1: agg1[dst] += h[src] * dinv[src]*dinv[dst]
// One warp per edge; 32 lanes x float4 = 128 floats. Vector red into L2.
// ---------------------------------------------------------------------------
__global__ __launch_bounds__(256) void k_scatter1(const int* __restrict__ src,
                                                  const int* __restrict__ dst) {
    int gtid = blockIdx.x * blockDim.x + threadIdx.x;
    int e    = gtid >> 5;
    int lane = threadIdx.x & 31;
    if (e >= N_EDGES) return;

    int s = src[e];
    int d = dst[e];
    float w = g_dinv[s] * g_dinv[d];

    float4 v = *(const float4*)(g_h + (size_t)s * D_HID + lane * 4);
    red_add_v4(g_agg1 + (size_t)d * D_HID + lane * 4,
               v.x * w, v.y * w, v.z * w, v.w * w);
}

// ---------------------------------------------------------------------------
// GEMM2: h2 = relu(agg1 + b1) @ W2   (M=100000, K=128, N=64)
// A-tile load fuses bias + relu. Epilogue writes g_h2 and initializes
// d_out = h2*dinv^2 + b2 (so scatter2 reduces directly into d_out).
// 128x64x8 tile, 256 threads, 8x4 per thread.
// ---------------------------------------------------------------------------
__global__ __launch_bounds__(256) void k_gemm2(const float* __restrict__ b1,
                                               const float* __restrict__ W2,
                                               const float* __restrict__ b2,
                                               float* __restrict__ out) {
    const int BM = 128, BK = 8;
    __shared__ __align__(16) float As[BK][BM];
    __shared__ __align__(16) float Bs[BK][D_OUT];

    int block_row = blockIdx.x * BM;
    int t  = threadIdx.x;
    int tx = t & 15;                 // 16 * 4 = 64 cols
    int ty = t >> 4;                 // 16 * 8 = 128 rows

    int arow = t >> 1;
    int acol = (t & 1) * 4;
    int brow = t >> 5;               // 8 rows
    int bcol = (t & 31) * 2;         // 64 cols via float2

    float acc[8][4];
#pragma unroll
    for (int i = 0; i < 8; i++)
#pragma unroll
        for (int j = 0; j < 4; j++) acc[i][j] = 0.0f;

    for (int k0 = 0; k0 < D_HID; k0 += BK) {
        int gr = block_row + arow;
        float4 a = make_float4(0.f, 0.f, 0.f, 0.f);
        if (gr < N_NODES) {
            float4 raw = *(const float4*)(g_agg1 + (size_t)gr * D_HID + k0 + acol);
            float4 bb  = *(const float4*)(b1 + k0 + acol);
            a.x = fmaxf(raw.x + bb.x, 0.0f);
            a.y = fmaxf(raw.y + bb.y, 0.0f);
            a.z = fmaxf(raw.z + bb.z, 0.0f);
            a.w = fmaxf(raw.w + bb.w, 0.0f);
        }
        As[acol + 0][arow] = a.x;
        As[acol + 1][arow] = a.y;
        As[acol + 2][arow] = a.z;
        As[acol + 3][arow] = a.w;

        *(float2*)&Bs[brow][bcol] =
            *(const float2*)(W2 + (size_t)(k0 + brow) * D_OUT + bcol);
        __syncthreads();

#pragma unroll
        for (int k = 0; k < BK; k++) {
            float4 a0 = *(float4*)&As[k][ty * 8];
            float4 a1 = *(float4*)&As[k][ty * 8 + 4];
            float4 b0 = *(float4*)&Bs[k][tx * 4];
            float ra[8] = {a0.x, a0.y, a0.z, a0.w, a1.x, a1.y, a1.z, a1.w};
            float rb[4] = {b0.x, b0.y, b0.z, b0.w};
#pragma unroll
            for (int i = 0; i < 8; i++)
#pragma unroll
                for (int j = 0; j < 4; j++) acc[i][j] += ra[i] * rb[j];
        }
        __syncthreads();
    }

    float4 bias = *(const float4*)(b2 + tx * 4);
#pragma unroll
    for (int i = 0; i < 8; i++) {
        int row = block_row + ty * 8 + i;
        if (row >= N_NODES) break;
        float di  = g_dinv[row];
        float di2 = di * di;
        size_t base = (size_t)row * D_OUT + tx * 4;
        float4 v = make_float4(acc[i][0], acc[i][1], acc[i][2], acc[i][3]);
        *(float4*)(g_h2 + base) = v;
        float4 o = make_float4(v.x * di2 + bias.x, v.y * di2 + bias.y,
                               v.z * di2 + bias.z, v.w * di2 + bias.w);
        *(float4*)(out + base) = o;
    }
}

// ---------------------------------------------------------------------------
// Scatter layer 2: out[dst] += h2[src] * dinv[src]*dinv[dst]
// One warp per TWO edges: half-warp (16 lanes x float4 = 64 floats) per edge.
// ---------------------------------------------------------------------------
__global__ __launch_bounds__(256) void k_scatter2(const int* __restrict__ src,
                                                  const int* __restrict__ dst,
                                                  float* __restrict__ out) {
    int gtid = blockIdx.x * blockDim.x + threadIdx.x;
    int warp = gtid >> 5;
    int lane = threadIdx.x & 31;
    int e    = warp * 2 + (lane >> 4);
    int sub  = lane & 15;
    if (e >= N_EDGES) return;

    int s = src[e];
    int d = dst[e];
    float w = g_dinv[s] * g_dinv[d];

    float4 v = *(const float4*)(g_h2 + (size_t)s * D_OUT + sub * 4);
    red_add_v4(out + (size_t)d * D_OUT + sub * 4,
               v.x * w, v.y * w, v.z * w, v.w * w);
}

// ---------------------------------------------------------------------------
// Launch sequence (all default-stream, graph-capturable: kernels only)
// ---------------------------------------------------------------------------
extern "C" void kernel_launch(void* const* d_in, const int* in_sizes, int n_in,
                              void* d_out, int out_size) {
    const float* x   = (const float*)d_in[0];
    const int*   ei  = (const int*)d_in[1];   // [2, E] int32 (JAX x64 disabled)
    const float* W1  = (const float*)d_in[2];
    const float* b1  = (const float*)d_in[3];
    const float* W2  = (const float*)d_in[4];
    const float* b2  = (const float*)d_in[5];
    float*       out = (float*)d_out;

    const int* src = ei;
    const int* dst = ei + N_EDGES;

    // degree + normalization
    k_zero_deg <<<(N_NODES + 255) / 256, 256>>>();
    k_count_deg<<<(N_EDGES + 255) / 256, 256>>>(dst);
    k_dinv     <<<(N_NODES + 255) / 256, 256>>>();

    // layer 1
    int gemm_blocks = (N_NODES + 127) / 128;            // 782
    k_gemm1   <<<gemm_blocks, 256>>>(x, W1);
    k_scatter1<<<(N_EDGES * 32 + 255) / 256, 256>>>(src, dst);   // 200000 blocks

    // layer 2 (bias1+relu fused into GEMM2 A-load; bias2 + self-loop in epilogue)
    k_gemm2   <<<gemm_blocks, 256>>>(b1, W2, b2, out);
    k_scatter2<<<((N_EDGES / 2) * 32 + 255) / 256, 256>>>(src, dst, out); // 100000 blocks
}

// round 8
// speedup vs baseline: 1.0502x; 1.0502x over previous
#include <cuda_runtime.h>
#include <cuda_bf16.h>
#include <mma.h>
#include <cstdint>

using namespace nvcuda;

// Problem constants (fixed by the reference).
#define N_NODES 100000
#define N_EDGES 1600000
#define D_IN    256
#define D_HID   128
#define D_OUT   64

// edge_index is int32 (JAX x64 disabled silently downgrades the requested int64).
// tcgen05 is NOT available: harness compiles at base sm_103 target (no 'a'
// feature set). Tensor path = legacy wmma/mma.sync HMMA (sm_80+ feature).

// ---------------------------------------------------------------------------
// Scratch (static __device__ globals — no allocation allowed in this harness)
// ---------------------------------------------------------------------------
__device__ __align__(16) float g_h   [(size_t)N_NODES * D_HID];  // x @ W1
__device__ __align__(16) float g_agg1[(size_t)N_NODES * D_HID];  // aggregated layer-1
__device__ __align__(16) float g_h2  [(size_t)N_NODES * D_OUT];  // relu(agg1+b1) @ W2
__device__ float g_dinv[N_NODES];
__device__ int   g_deg [N_NODES];

// ---------------------------------------------------------------------------
// Vector global reduction: red.global.add.v4.f32 (sm_90+)
// ---------------------------------------------------------------------------
__device__ __forceinline__ void red_add_v4(float* p, float a, float b, float c, float d) {
    asm volatile("red.global.add.v4.f32 [%0], {%1, %2, %3, %4};"
                 :: "l"(p), "f"(a), "f"(b), "f"(c), "f"(d) : "memory");
}

// ---------------------------------------------------------------------------
// Degree / normalization
// ---------------------------------------------------------------------------
__global__ void k_zero_deg() {
    int i = blockIdx.x * blockDim.x + threadIdx.x;
    if (i < N_NODES) g_deg[i] = 0;
}
__global__ void k_count_deg(const int* __restrict__ dst) {
    int e = blockIdx.x * blockDim.x + threadIdx.x;
    if (e < N_EDGES) atomicAdd(&g_deg[dst[e]], 1);
}
__global__ void k_dinv() {
    int i = blockIdx.x * blockDim.x + threadIdx.x;
    if (i < N_NODES) g_dinv[i] = rsqrtf(1.0f + (float)g_deg[i]);
}

// ---------------------------------------------------------------------------
// GEMM1 (wmma bf16, 3-term split): h = x @ W1   (M=100000, K=256, N=128)
//   h = xh@Wh + xh@Wl + xl@Wh  (fp32 accumulate; dropped xl@Wl ~2^-18)
// 128x128 CTA tile, 8 warps (4x2), each warp 32x64 = 2x4 m16n16k16 tiles.
// K in 8 chunks of 32. Epilogue stages fp32 C in smem (two 64-row passes),
// writes g_h and g_agg1 = h*dinv^2 (self-loop init).
// ---------------------------------------------------------------------------
#define G1_LDA 40     // 32 k + 8 pad (bf16 elems; mult of 8 for wmma)
#define G1_LDB 136    // 128 n + 8 pad
#define G1_LDC 132    // 128 + 4 pad (f32; mult of 4)

// smem carve (bytes):
//   Ah: 128*40*2 = 10240   @ 0
//   Al: 10240              @ 10240
//   Bh: 32*136*2 = 8704    @ 20480
//   Bl: 8704               @ 29184   -> tiles end 37888
//   Cs (epilogue, reuses from 0): 64*132*4 = 33792
#define G1_SMEM_BYTES 37888

__global__ __launch_bounds__(256) void k_gemm1_w(const float* __restrict__ x,
                                                 const float* __restrict__ W1) {
    __shared__ __align__(16) char smem_raw[G1_SMEM_BYTES];
    __nv_bfloat16 (*Ah)[G1_LDA] = (__nv_bfloat16(*)[G1_LDA])(smem_raw);
    __nv_bfloat16 (*Al)[G1_LDA] = (__nv_bfloat16(*)[G1_LDA])(smem_raw + 10240);
    __nv_bfloat16 (*Bh)[G1_LDB] = (__nv_bfloat16(*)[G1_LDB])(smem_raw + 20480);
    __nv_bfloat16 (*Bl)[G1_LDB] = (__nv_bfloat16(*)[G1_LDB])(smem_raw + 29184);
    float        (*Cs)[G1_LDC]  = (float(*)[G1_LDC])(smem_raw);

    const int t    = threadIdx.x;
    const int wid  = t >> 5;
    const int warp_m = wid >> 1;          // 0..3  (32-row band)
    const int warp_n = wid & 1;           // 0..1  (64-col band)
    const int block_row = blockIdx.x * 128;

    // A load map: row = t>>1 (0..127), k-quarter = (t&1)*16
    const int arow = t >> 1;
    const int akq  = (t & 1) * 16;
    const int gr   = block_row + arow;
    const bool avalid = (gr < N_NODES);

    // B load map: k = t>>3 (0..31), n-quarter = (t&7)*16
    const int bk  = t >> 3;
    const int bnq = (t & 7) * 16;

    wmma::fragment<wmma::accumulator, 16, 16, 16, float> acc[2][4];
#pragma unroll
    for (int mt = 0; mt < 2; mt++)
#pragma unroll
        for (int nt = 0; nt < 4; nt++) wmma::fill_fragment(acc[mt][nt], 0.0f);

    for (int c = 0; c < D_IN / 32; c++) {          // 8 chunks of K=32
        const int k0 = c * 32;

        // ---- A tile: x[block_row..+127][k0..+31] -> bf16 hi/lo
        {
            const float4* xp = (const float4*)(x + (size_t)gr * D_IN + k0 + akq);
#pragma unroll
            for (int i = 0; i < 4; i++) {
                float4 v = avalid ? xp[i] : make_float4(0.f, 0.f, 0.f, 0.f);
                __nv_bfloat16 hx = __float2bfloat16_rn(v.x);
                __nv_bfloat16 hy = __float2bfloat16_rn(v.y);
                __nv_bfloat16 hz = __float2bfloat16_rn(v.z);
                __nv_bfloat16 hw = __float2bfloat16_rn(v.w);
                __nv_bfloat16 lx = __float2bfloat16_rn(v.x - __bfloat162float(hx));
                __nv_bfloat16 ly = __float2bfloat16_rn(v.y - __bfloat162float(hy));
                __nv_bfloat16 lz = __float2bfloat16_rn(v.z - __bfloat162float(hz));
                __nv_bfloat16 lw = __float2bfloat16_rn(v.w - __bfloat162float(hw));
                int kc = akq + i * 4;
                *(__nv_bfloat162*)&Ah[arow][kc]     = __nv_bfloat162(hx, hy);
                *(__nv_bfloat162*)&Ah[arow][kc + 2] = __nv_bfloat162(hz, hw);
                *(__nv_bfloat162*)&Al[arow][kc]     = __nv_bfloat162(lx, ly);
                *(__nv_bfloat162*)&Al[arow][kc + 2] = __nv_bfloat162(lz, lw);
            }
        }
        // ---- B tile: W1[k0..+31][0..127] -> bf16 hi/lo (row-major [k][n])
        {
            const float4* wp = (const float4*)(W1 + (size_t)(k0 + bk) * D_HID + bnq);
#pragma unroll
            for (int i = 0; i < 4; i++) {
                float4 v = wp[i];
                __nv_bfloat16 hx = __float2bfloat16_rn(v.x);
                __nv_bfloat16 hy = __float2bfloat16_rn(v.y);
                __nv_bfloat16 hz = __float2bfloat16_rn(v.z);
                __nv_bfloat16 hw = __float2bfloat16_rn(v.w);
                __nv_bfloat16 lx = __float2bfloat16_rn(v.x - __bfloat162float(hx));
                __nv_bfloat16 ly = __float2bfloat16_rn(v.y - __bfloat162float(hy));
                __nv_bfloat16 lz = __float2bfloat16_rn(v.z - __bfloat162float(hz));
                __nv_bfloat16 lw = __float2bfloat16_rn(v.w - __bfloat162float(hw));
                int nc = bnq + i * 4;
                *(__nv_bfloat162*)&Bh[bk][nc]     = __nv_bfloat162(hx, hy);
                *(__nv_bfloat162*)&Bh[bk][nc + 2] = __nv_bfloat162(hz, hw);
                *(__nv_bfloat162*)&Bl[bk][nc]     = __nv_bfloat162(lx, ly);
                *(__nv_bfloat162*)&Bl[bk][nc + 2] = __nv_bfloat162(lz, lw);
            }
        }
        __syncthreads();

        // ---- MMA: 2 k-steps of 16; preload B frags, then per-mt A frags
#pragma unroll
        for (int ks = 0; ks < 32; ks += 16) {
            wmma::fragment<wmma::matrix_b, 16, 16, 16, __nv_bfloat16, wmma::row_major> fBh[4], fBl[4];
#pragma unroll
            for (int nt = 0; nt < 4; nt++) {
                int col = warp_n * 64 + nt * 16;
                wmma::load_matrix_sync(fBh[nt], &Bh[ks][col], G1_LDB);
                wmma::load_matrix_sync(fBl[nt], &Bl[ks][col], G1_LDB);
            }
#pragma unroll
            for (int mt = 0; mt < 2; mt++) {
                int row = warp_m * 32 + mt * 16;
                wmma::fragment<wmma::matrix_a, 16, 16, 16, __nv_bfloat16, wmma::row_major> fAh, fAl;
                wmma::load_matrix_sync(fAh, &Ah[row][ks], G1_LDA);
                wmma::load_matrix_sync(fAl, &Al[row][ks], G1_LDA);
#pragma unroll
                for (int nt = 0; nt < 4; nt++) {
                    wmma::mma_sync(acc[mt][nt], fAh, fBh[nt], acc[mt][nt]);
                    wmma::mma_sync(acc[mt][nt], fAh, fBl[nt], acc[mt][nt]);
                    wmma::mma_sync(acc[mt][nt], fAl, fBh[nt], acc[mt][nt]);
                }
            }
        }
        __syncthreads();
    }

    // ---- Epilogue: two 64-row passes through smem staging (bounds-safe)
    for (int pass = 0; pass < 2; pass++) {
        if ((warp_m >> 1) == pass) {
            int r0 = (warp_m & 1) * 32;
#pragma unroll
            for (int mt = 0; mt < 2; mt++)
#pragma unroll
                for (int nt = 0; nt < 4; nt++)
                    wmma::store_matrix_sync(&Cs[r0 + mt * 16][warp_n * 64 + nt * 16],
                                            acc[mt][nt], G1_LDC, wmma::mem_row_major);
        }
        __syncthreads();

        int rr = t >> 2;               // 0..63
        int cq = (t & 3) * 32;         // 32-float quarter
        int grow = block_row + pass * 64 + rr;
        if (grow < N_NODES) {
            float di  = g_dinv[grow];
            float di2 = di * di;
            size_t base = (size_t)grow * D_HID + cq;
#pragma unroll
            for (int i = 0; i < 8; i++) {
                float4 v = *(float4*)&Cs[rr][cq + i * 4];
                *(float4*)(g_h + base + i * 4) = v;
                *(float4*)(g_agg1 + base + i * 4) =
                    make_float4(v.x * di2, v.y * di2, v.z * di2, v.w * di2);
            }
        }
        __syncthreads();
    }
}

// ---------------------------------------------------------------------------
// Scatter layer 1: agg1[dst] += h[src] * dinv[src]*dinv[dst]
// One warp per edge; 32 lanes x float4 = 128 floats. Vector red into L2.
// ---------------------------------------------------------------------------
__global__ __launch_bounds__(256) void k_scatter1(const int* __restrict__ src,
                                                  const int* __restrict__ dst) {
    int gtid = blockIdx.x * blockDim.x + threadIdx.x;
    int e    = gtid >> 5;
    int lane = threadIdx.x & 31;
    if (e >= N_EDGES) return;

    int s = src[e];
    int d = dst[e];
    float w = g_dinv[s] * g_dinv[d];

    float4 v = *(const float4*)(g_h + (size_t)s * D_HID + lane * 4);
    red_add_v4(g_agg1 + (size_t)d * D_HID + lane * 4,
               v.x * w, v.y * w, v.z * w, v.w * w);
}

// ---------------------------------------------------------------------------
// GEMM2: h2 = relu(agg1 + b1) @ W2   (M=100000, K=128, N=64)  — SIMT fp32
// A-tile load fuses bias+relu; epilogue writes g_h2 and out = h2*dinv^2 + b2.
// ---------------------------------------------------------------------------
__global__ __launch_bounds__(256) void k_gemm2(const float* __restrict__ b1,
                                               const float* __restrict__ W2,
                                               const float* __restrict__ b2,
                                               float* __restrict__ out) {
    const int BM = 128, BK = 8;
    __shared__ __align__(16) float As[BK][BM];
    __shared__ __align__(16) float Bs[BK][D_OUT];

    int block_row = blockIdx.x * BM;
    int t  = threadIdx.x;
    int tx = t & 15;
    int ty = t >> 4;

    int arow = t >> 1;
    int acol = (t & 1) * 4;
    int brow = t >> 5;
    int bcol = (t & 31) * 2;

    float acc[8][4];
#pragma unroll
    for (int i = 0; i < 8; i++)
#pragma unroll
        for (int j = 0; j < 4; j++) acc[i][j] = 0.0f;

    for (int k0 = 0; k0 < D_HID; k0 += BK) {
        int gr = block_row + arow;
        float4 a = make_float4(0.f, 0.f, 0.f, 0.f);
        if (gr < N_NODES) {
            float4 raw = *(const float4*)(g_agg1 + (size_t)gr * D_HID + k0 + acol);
            float4 bb  = *(const float4*)(b1 + k0 + acol);
            a.x = fmaxf(raw.x + bb.x, 0.0f);
            a.y = fmaxf(raw.y + bb.y, 0.0f);
            a.z = fmaxf(raw.z + bb.z, 0.0f);
            a.w = fmaxf(raw.w + bb.w, 0.0f);
        }
        As[acol + 0][arow] = a.x;
        As[acol + 1][arow] = a.y;
        As[acol + 2][arow] = a.z;
        As[acol + 3][arow] = a.w;

        *(float2*)&Bs[brow][bcol] =
            *(const float2*)(W2 + (size_t)(k0 + brow) * D_OUT + bcol);
        __syncthreads();

#pragma unroll
        for (int k = 0; k < BK; k++) {
            float4 a0 = *(float4*)&As[k][ty * 8];
            float4 a1 = *(float4*)&As[k][ty * 8 + 4];
            float4 b0 = *(float4*)&Bs[k][tx * 4];
            float ra[8] = {a0.x, a0.y, a0.z, a0.w, a1.x, a1.y, a1.z, a1.w};
            float rb[4] = {b0.x, b0.y, b0.z, b0.w};
#pragma unroll
            for (int i = 0; i < 8; i++)
#pragma unroll
                for (int j = 0; j < 4; j++) acc[i][j] += ra[i] * rb[j];
        }
        __syncthreads();
    }

    float4 bias = *(const float4*)(b2 + tx * 4);
#pragma unroll
    for (int i = 0; i < 8; i++) {
        int row = block_row + ty * 8 + i;
        if (row >= N_NODES) break;
        float di  = g_dinv[row];
        float di2 = di * di;
        size_t base = (size_t)row * D_OUT + tx * 4;
        float4 v = make_float4(acc[i][0], acc[i][1], acc[i][2], acc[i][3]);
        *(float4*)(g_h2 + base) = v;
        float4 o = make_float4(v.x * di2 + bias.x, v.y * di2 + bias.y,
                               v.z * di2 + bias.z, v.w * di2 + bias.w);
        *(float4*)(out + base) = o;
    }
}

// ---------------------------------------------------------------------------
// Scatter layer 2: out[dst] += h2[src] * dinv[src]*dinv[dst]
// One warp per TWO edges (16 lanes x float4 = 64 floats each).
// ---------------------------------------------------------------------------
__global__ __launch_bounds__(256) void k_scatter2(const int* __restrict__ src,
                                                  const int* __restrict__ dst,
                                                  float* __restrict__ out) {
    int gtid = blockIdx.x * blockDim.x + threadIdx.x;
    int warp = gtid >> 5;
    int lane = threadIdx.x & 31;
    int e    = warp * 2 + (lane >> 4);
    int sub  = lane & 15;
    if (e >= N_EDGES) return;

    int s = src[e];
    int d = dst[e];
    float w = g_dinv[s] * g_dinv[d];

    float4 v = *(const float4*)(g_h2 + (size_t)s * D_OUT + sub * 4);
    red_add_v4(out + (size_t)d * D_OUT + sub * 4,
               v.x * w, v.y * w, v.z * w, v.w * w);
}

// ---------------------------------------------------------------------------
// Launch sequence (graph-capturable: kernel launches only)
// ---------------------------------------------------------------------------
extern "C" void kernel_launch(void* const* d_in, const int* in_sizes, int n_in,
                              void* d_out, int out_size) {
    const float* x   = (const float*)d_in[0];
    const int*   ei  = (const int*)d_in[1];   // [2, E] int32
    const float* W1  = (const float*)d_in[2];
    const float* b1  = (const float*)d_in[3];
    const float* W2  = (const float*)d_in[4];
    const float* b2  = (const float*)d_in[5];
    float*       out = (float*)d_out;

    const int* src = ei;
    const int* dst = ei + N_EDGES;

    // degree + normalization
    k_zero_deg <<<(N_NODES + 255) / 256, 256>>>();
    k_count_deg<<<(N_EDGES + 255) / 256, 256>>>(dst);
    k_dinv     <<<(N_NODES + 255) / 256, 256>>>();

    // layer 1 (wmma bf16-split GEMM + atomic scatter)
    int gemm_blocks = (N_NODES + 127) / 128;            // 782
    k_gemm1_w <<<gemm_blocks, 256>>>(x, W1);
    k_scatter1<<<(N_EDGES * 32 + 255) / 256, 256>>>(src, dst);

    // layer 2
    k_gemm2   <<<gemm_blocks, 256>>>(b1, W2, b2, out);
    k_scatter2<<<((N_EDGES / 2) * 32 + 255) / 256, 256>>>(src, dst, out);
}

// round 12
// speedup vs baseline: 1.0585x; 1.0079x over previous
#include <cuda_runtime.h>
#include <cuda_bf16.h>
#include <mma.h>
#include <cstdint>

using namespace nvcuda;

// Problem constants (fixed by the reference).
#define N_NODES 100000
#define N_EDGES 1600000
#define D_IN    256
#define D_HID   128
#define D_OUT   64

// edge_index is int32 (JAX x64 disabled). tcgen05 unavailable (harness targets
// base sm_103, no 'a' features) -> tensor path is wmma/HMMA (sm_80+).

// ---------------------------------------------------------------------------
// Scratch (static __device__ globals — no allocation allowed)
// g_hs  = h1 * dinv[row]      (pre-scaled so scatter needs only dinv[dst])
// g_agg1= aggregated layer-1 (init h1*dinv^2)
// g_hs2 = h2 * dinv[row]
// ---------------------------------------------------------------------------
__device__ __align__(16) float g_hs  [(size_t)N_NODES * D_HID];
__device__ __align__(16) float g_agg1[(size_t)N_NODES * D_HID];
__device__ __align__(16) float g_hs2 [(size_t)N_NODES * D_OUT];
__device__ float g_dinv[N_NODES];
__device__ int   g_deg [N_NODES];

__device__ __forceinline__ void red_add_v4(float* p, float a, float b, float c, float d) {
    asm volatile("red.global.add.v4.f32 [%0], {%1, %2, %3, %4};"
                 :: "l"(p), "f"(a), "f"(b), "f"(c), "f"(d) : "memory");
}

__device__ __forceinline__ void cvt_split(float v, __nv_bfloat16& h, __nv_bfloat16& l) {
    h = __float2bfloat16_rn(v);
    l = __float2bfloat16_rn(v - __bfloat162float(h));
}

// ---------------------------------------------------------------------------
// Degree / normalization
// ---------------------------------------------------------------------------
__global__ void k_zero_deg() {
    int i = blockIdx.x * blockDim.x + threadIdx.x;
    if (i < N_NODES) g_deg[i] = 0;
}
__global__ void k_count_deg(const int* __restrict__ dst) {
    int e = blockIdx.x * blockDim.x + threadIdx.x;
    if (e < N_EDGES) atomicAdd(&g_deg[dst[e]], 1);
}
__global__ void k_dinv() {
    int i = blockIdx.x * blockDim.x + threadIdx.x;
    if (i < N_NODES) g_dinv[i] = rsqrtf(1.0f + (float)g_deg[i]);
}

// ---------------------------------------------------------------------------
// GEMM1 (wmma bf16 3-term split, software-pipelined):
//   h = x @ W1 ; writes g_hs = h*dinv, g_agg1 = h*dinv^2
// 128x128 CTA tile, 8 warps (4x2), warp = 32x64 = 2x4 m16n16k16 frags.
// K=256 in 8 chunks of 32. Pipeline: LDG(c+1) -> MMA(c) -> cvt+STS(c+1) -> sync
// with double-buffered smem tiles (dynamic smem, 74 KB).
// ---------------------------------------------------------------------------
#define G1_LDA 40
#define G1_LDB 136
#define G1_LDC 132
// per-buffer: Ah 10240 @0, Al 10240 @10240, Bh 8704 @20480, Bl 8704 @29184
#define G1_BUF  37888
#define G1_SMEM (2 * G1_BUF)

__global__ __launch_bounds__(256) void k_gemm1_w(const float* __restrict__ x,
                                                 const float* __restrict__ W1) {
    extern __shared__ __align__(16) char smem[];

    const int t      = threadIdx.x;
    const int wid    = t >> 5;
    const int warp_m = wid >> 1;
    const int warp_n = wid & 1;
    const int block_row = blockIdx.x * 128;

    const int arow = t >> 1;
    const int akq  = (t & 1) * 16;
    const int gr   = block_row + arow;
    const bool avalid = (gr < N_NODES);

    const int bk  = t >> 3;
    const int bnq = (t & 7) * 16;

    const float4* xrow = (const float4*)(x + (size_t)gr * D_IN + akq);
    const float4* wrow = (const float4*)(W1 + (size_t)bk * D_HID + bnq);

    wmma::fragment<wmma::accumulator, 16, 16, 16, float> acc[2][4];
#pragma unroll
    for (int mt = 0; mt < 2; mt++)
#pragma unroll
        for (int nt = 0; nt < 4; nt++) wmma::fill_fragment(acc[mt][nt], 0.0f);

    float4 ra[4], rb[4];

    auto load_chunk = [&](int c) {
#pragma unroll
        for (int i = 0; i < 4; i++)
            ra[i] = avalid ? xrow[c * 8 + i] : make_float4(0.f, 0.f, 0.f, 0.f);
        // chunk advance for B = 32 rows of W1 = 32 * (D_HID/4) float4
        // (R11 bug: used 8 * (D_HID/4) -> wrong W1 rows for chunks 1..7)
#pragma unroll
        for (int i = 0; i < 4; i++)
            rb[i] = wrow[(size_t)c * 32 * (D_HID / 4) + i];
    };
    auto store_chunk = [&](int b) {
        char* base = smem + b * G1_BUF;
        __nv_bfloat16 (*Ah)[G1_LDA] = (__nv_bfloat16(*)[G1_LDA])(base);
        __nv_bfloat16 (*Al)[G1_LDA] = (__nv_bfloat16(*)[G1_LDA])(base + 10240);
        __nv_bfloat16 (*Bh)[G1_LDB] = (__nv_bfloat16(*)[G1_LDB])(base + 20480);
        __nv_bfloat16 (*Bl)[G1_LDB] = (__nv_bfloat16(*)[G1_LDB])(base + 29184);
#pragma unroll
        for (int i = 0; i < 4; i++) {
            __nv_bfloat16 hx, hy, hz, hw, lx, ly, lz, lw;
            cvt_split(ra[i].x, hx, lx); cvt_split(ra[i].y, hy, ly);
            cvt_split(ra[i].z, hz, lz); cvt_split(ra[i].w, hw, lw);
            int kc = akq + i * 4;
            *(__nv_bfloat162*)&Ah[arow][kc]     = __nv_bfloat162(hx, hy);
            *(__nv_bfloat162*)&Ah[arow][kc + 2] = __nv_bfloat162(hz, hw);
            *(__nv_bfloat162*)&Al[arow][kc]     = __nv_bfloat162(lx, ly);
            *(__nv_bfloat162*)&Al[arow][kc + 2] = __nv_bfloat162(lz, lw);
        }
#pragma unroll
        for (int i = 0; i < 4; i++) {
            __nv_bfloat16 hx, hy, hz, hw, lx, ly, lz, lw;
            cvt_split(rb[i].x, hx, lx); cvt_split(rb[i].y, hy, ly);
            cvt_split(rb[i].z, hz, lz); cvt_split(rb[i].w, hw, lw);
            int nc = bnq + i * 4;
            *(__nv_bfloat162*)&Bh[bk][nc]     = __nv_bfloat162(hx, hy);
            *(__nv_bfloat162*)&Bh[bk][nc + 2] = __nv_bfloat162(hz, hw);
            *(__nv_bfloat162*)&Bl[bk][nc]     = __nv_bfloat162(lx, ly);
            *(__nv_bfloat162*)&Bl[bk][nc + 2] = __nv_bfloat162(lz, lw);
        }
    };

    load_chunk(0);
    store_chunk(0);
    __syncthreads();

    for (int c = 0; c < D_IN / 32; c++) {
        if (c < D_IN / 32 - 1) load_chunk(c + 1);      // LDG issues early

        char* base = smem + (c & 1) * G1_BUF;
        __nv_bfloat16 (*Ah)[G1_LDA] = (__nv_bfloat16(*)[G1_LDA])(base);
        __nv_bfloat16 (*Al)[G1_LDA] = (__nv_bfloat16(*)[G1_LDA])(base + 10240);
        __nv_bfloat16 (*Bh)[G1_LDB] = (__nv_bfloat16(*)[G1_LDB])(base + 20480);
        __nv_bfloat16 (*Bl)[G1_LDB] = (__nv_bfloat16(*)[G1_LDB])(base + 29184);

#pragma unroll
        for (int ks = 0; ks < 32; ks += 16) {
            wmma::fragment<wmma::matrix_b, 16, 16, 16, __nv_bfloat16, wmma::row_major> fBh[4], fBl[4];
#pragma unroll
            for (int nt = 0; nt < 4; nt++) {
                int col = warp_n * 64 + nt * 16;
                wmma::load_matrix_sync(fBh[nt], &Bh[ks][col], G1_LDB);
                wmma::load_matrix_sync(fBl[nt], &Bl[ks][col], G1_LDB);
            }
#pragma unroll
            for (int mt = 0; mt < 2; mt++) {
                int row = warp_m * 32 + mt * 16;
                wmma::fragment<wmma::matrix_a, 16, 16, 16, __nv_bfloat16, wmma::row_major> fAh, fAl;
                wmma::load_matrix_sync(fAh, &Ah[row][ks], G1_LDA);
                wmma::load_matrix_sync(fAl, &Al[row][ks], G1_LDA);
#pragma unroll
                for (int nt = 0; nt < 4; nt++) {
                    wmma::mma_sync(acc[mt][nt], fAh, fBh[nt], acc[mt][nt]);
                    wmma::mma_sync(acc[mt][nt], fAh, fBl[nt], acc[mt][nt]);
                    wmma::mma_sync(acc[mt][nt], fAl, fBh[nt], acc[mt][nt]);
                }
            }
        }
        if (c < D_IN / 32 - 1) store_chunk((c + 1) & 1);
        __syncthreads();
    }

    // Epilogue: two 64-row passes through smem (reuses buffer 0 region).
    float (*Cs)[G1_LDC] = (float(*)[G1_LDC])(smem);
    for (int pass = 0; pass < 2; pass++) {
        if ((warp_m >> 1) == pass) {
            int r0 = (warp_m & 1) * 32;
#pragma unroll
            for (int mt = 0; mt < 2; mt++)
#pragma unroll
                for (int nt = 0; nt < 4; nt++)
                    wmma::store_matrix_sync(&Cs[r0 + mt * 16][warp_n * 64 + nt * 16],
                                            acc[mt][nt], G1_LDC, wmma::mem_row_major);
        }
        __syncthreads();

        int rr = t >> 2;
        int cq = (t & 3) * 32;
        int grow = block_row + pass * 64 + rr;
        if (grow < N_NODES) {
            float di  = g_dinv[grow];
            float di2 = di * di;
            size_t base = (size_t)grow * D_HID + cq;
#pragma unroll
            for (int i = 0; i < 8; i++) {
                float4 v = *(float4*)&Cs[rr][cq + i * 4];
                *(float4*)(g_hs + base + i * 4) =
                    make_float4(v.x * di, v.y * di, v.z * di, v.w * di);
                *(float4*)(g_agg1 + base + i * 4) =
                    make_float4(v.x * di2, v.y * di2, v.z * di2, v.w * di2);
            }
        }
        __syncthreads();
    }
}

// ---------------------------------------------------------------------------
// Scatter layer 1: agg1[dst] += hs[src] * dinv[dst]   (hs pre-scaled by dinv[src])
// One warp per edge; 32 lanes x float4 = 128 floats.
// ---------------------------------------------------------------------------
__global__ __launch_bounds__(256) void k_scatter1(const int* __restrict__ src,
                                                  const int* __restrict__ dst) {
    int gtid = blockIdx.x * blockDim.x + threadIdx.x;
    int e    = gtid >> 5;
    int lane = threadIdx.x & 31;
    if (e >= N_EDGES) return;

    int s = src[e];
    int d = dst[e];
    float w = g_dinv[d];

    float4 v = *(const float4*)(g_hs + (size_t)s * D_HID + lane * 4);
    red_add_v4(g_agg1 + (size_t)d * D_HID + lane * 4,
               v.x * w, v.y * w, v.z * w, v.w * w);
}

// ---------------------------------------------------------------------------
// GEMM2 (wmma bf16 3-term split): h2 = relu(agg1+b1) @ W2  (K=128, N=64)
// 128x64 CTA tile, 8 warps (4x2), warp = 32x32 = 2x2 frags, K chunks of 32.
// bias+relu fused into A convert. Epilogue: g_hs2 = h2*dinv,
// out = h2*dinv^2 + b2 (scatter2 then reduces into out).
// ---------------------------------------------------------------------------
#define G2_LDA 40
#define G2_LDB 72
#define G2_LDC 68

__global__ __launch_bounds__(256) void k_gemm2_w(const float* __restrict__ b1,
                                                 const float* __restrict__ W2,
                                                 const float* __restrict__ b2,
                                                 float* __restrict__ out) {
    __shared__ __align__(16) union {
        struct {
            __nv_bfloat16 Ah[128][G2_LDA];
            __nv_bfloat16 Al[128][G2_LDA];
            __nv_bfloat16 Bh[32][G2_LDB];
            __nv_bfloat16 Bl[32][G2_LDB];
        } tiles;
        float Cs[128][G2_LDC];
    } sm;

    const int t      = threadIdx.x;
    const int wid    = t >> 5;
    const int warp_m = wid >> 1;
    const int warp_n = wid & 1;
    const int block_row = blockIdx.x * 128;

    const int arow = t >> 1;
    const int akq  = (t & 1) * 16;
    const int gr   = block_row + arow;
    const bool avalid = (gr < N_NODES);

    const int bk = t >> 3;          // 0..31
    const int bq = (t & 7) * 8;     // 8-float span of the 64 cols

    wmma::fragment<wmma::accumulator, 16, 16, 16, float> acc[2][2];
#pragma unroll
    for (int mt = 0; mt < 2; mt++)
#pragma unroll
        for (int nt = 0; nt < 2; nt++) wmma::fill_fragment(acc[mt][nt], 0.0f);

    for (int c = 0; c < D_HID / 32; c++) {      // 4 chunks
        const int k0 = c * 32;
        // A: relu(agg1 + b1) -> bf16 hi/lo
        {
            const float4* ap = (const float4*)(g_agg1 + (size_t)gr * D_HID + k0 + akq);
            const float4* bp = (const float4*)(b1 + k0 + akq);
#pragma unroll
            for (int i = 0; i < 4; i++) {
                float4 v  = avalid ? ap[i] : make_float4(0.f, 0.f, 0.f, 0.f);
                float4 bb = bp[i];
                v.x = fmaxf(v.x + bb.x, 0.f); v.y = fmaxf(v.y + bb.y, 0.f);
                v.z = fmaxf(v.z + bb.z, 0.f); v.w = fmaxf(v.w + bb.w, 0.f);
                __nv_bfloat16 hx, hy, hz, hw, lx, ly, lz, lw;
                cvt_split(v.x, hx, lx); cvt_split(v.y, hy, ly);
                cvt_split(v.z, hz, lz); cvt_split(v.w, hw, lw);
                int kc = akq + i * 4;
                *(__nv_bfloat162*)&sm.tiles.Ah[arow][kc]     = __nv_bfloat162(hx, hy);
                *(__nv_bfloat162*)&sm.tiles.Ah[arow][kc + 2] = __nv_bfloat162(hz, hw);
                *(__nv_bfloat162*)&sm.tiles.Al[arow][kc]     = __nv_bfloat162(lx, ly);
                *(__nv_bfloat162*)&sm.tiles.Al[arow][kc + 2] = __nv_bfloat162(lz, lw);
            }
        }
        // B: W2[k0+bk][bq..bq+7] -> bf16 hi/lo
        {
            const float4* wp = (const float4*)(W2 + (size_t)(k0 + bk) * D_OUT + bq);
#pragma unroll
            for (int i = 0; i < 2; i++) {
                float4 v = wp[i];
                __nv_bfloat16 hx, hy, hz, hw, lx, ly, lz, lw;
                cvt_split(v.x, hx, lx); cvt_split(v.y, hy, ly);
                cvt_split(v.z, hz, lz); cvt_split(v.w, hw, lw);
                int nc = bq + i * 4;
                *(__nv_bfloat162*)&sm.tiles.Bh[bk][nc]     = __nv_bfloat162(hx, hy);
                *(__nv_bfloat162*)&sm.tiles.Bh[bk][nc + 2] = __nv_bfloat162(hz, hw);
                *(__nv_bfloat162*)&sm.tiles.Bl[bk][nc]     = __nv_bfloat162(lx, ly);
                *(__nv_bfloat162*)&sm.tiles.Bl[bk][nc + 2] = __nv_bfloat162(lz, lw);
            }
        }
        __syncthreads();

#pragma unroll
        for (int ks = 0; ks < 32; ks += 16) {
            wmma::fragment<wmma::matrix_b, 16, 16, 16, __nv_bfloat16, wmma::row_major> fBh[2], fBl[2];
#pragma unroll
            for (int nt = 0; nt < 2; nt++) {
                int col = warp_n * 32 + nt * 16;
                wmma::load_matrix_sync(fBh[nt], &sm.tiles.Bh[ks][col], G2_LDB);
                wmma::load_matrix_sync(fBl[nt], &sm.tiles.Bl[ks][col], G2_LDB);
            }
#pragma unroll
            for (int mt = 0; mt < 2; mt++) {
                int row = warp_m * 32 + mt * 16;
                wmma::fragment<wmma::matrix_a, 16, 16, 16, __nv_bfloat16, wmma::row_major> fAh, fAl;
                wmma::load_matrix_sync(fAh, &sm.tiles.Ah[row][ks], G2_LDA);
                wmma::load_matrix_sync(fAl, &sm.tiles.Al[row][ks], G2_LDA);
#pragma unroll
                for (int nt = 0; nt < 2; nt++) {
                    wmma::mma_sync(acc[mt][nt], fAh, fBh[nt], acc[mt][nt]);
                    wmma::mma_sync(acc[mt][nt], fAh, fBl[nt], acc[mt][nt]);
                    wmma::mma_sync(acc[mt][nt], fAl, fBh[nt], acc[mt][nt]);
                }
            }
        }
        __syncthreads();
    }

    // Epilogue: single pass through smem (128x68 fp32)
#pragma unroll
    for (int mt = 0; mt < 2; mt++)
#pragma unroll
        for (int nt = 0; nt < 2; nt++)
            wmma::store_matrix_sync(&sm.Cs[warp_m * 32 + mt * 16][warp_n * 32 + nt * 16],
                                    acc[mt][nt], G2_LDC, wmma::mem_row_major);
    __syncthreads();

    int rr = t >> 1;                 // 0..127
    int ch = (t & 1) * 32;           // column half
    int grow = block_row + rr;
    if (grow < N_NODES) {
        float di  = g_dinv[grow];
        float di2 = di * di;
        size_t base = (size_t)grow * D_OUT + ch;
#pragma unroll
        for (int i = 0; i < 8; i++) {
            float4 v  = *(float4*)&sm.Cs[rr][ch + i * 4];
            float4 bb = *(const float4*)(b2 + ch + i * 4);
            *(float4*)(g_hs2 + base + i * 4) =
                make_float4(v.x * di, v.y * di, v.z * di, v.w * di);
            *(float4*)(out + base + i * 4) =
                make_float4(v.x * di2 + bb.x, v.y * di2 + bb.y,
                            v.z * di2 + bb.z, v.w * di2 + bb.w);
        }
    }
}

// ---------------------------------------------------------------------------
// Scatter layer 2: out[dst] += hs2[src] * dinv[dst]
// One warp per TWO edges (16 lanes x float4 = 64 floats each).
// ---------------------------------------------------------------------------
__global__ __launch_bounds__(256) void k_scatter2(const int* __restrict__ src,
                                                  const int* __restrict__ dst,
                                                  float* __restrict__ out) {
    int gtid = blockIdx.x * blockDim.x + threadIdx.x;
    int warp = gtid >> 5;
    int lane = threadIdx.x & 31;
    int e    = warp * 2 + (lane >> 4);
    int sub  = lane & 15;
    if (e >= N_EDGES) return;

    int s = src[e];
    int d = dst[e];
    float w = g_dinv[d];

    float4 v = *(const float4*)(g_hs2 + (size_t)s * D_OUT + sub * 4);
    red_add_v4(out + (size_t)d * D_OUT + sub * 4,
               v.x * w, v.y * w, v.z * w, v.w * w);
}

// ---------------------------------------------------------------------------
// Launch sequence (graph-capturable: kernel launches only)
// ---------------------------------------------------------------------------
extern "C" void kernel_launch(void* const* d_in, const int* in_sizes, int n_in,
                              void* d_out, int out_size) {
    const float* x   = (const float*)d_in[0];
    const int*   ei  = (const int*)d_in[1];   // [2, E] int32
    const float* W1  = (const float*)d_in[2];
    const float* b1  = (const float*)d_in[3];
    const float* W2  = (const float*)d_in[4];
    const float* b2  = (const float*)d_in[5];
    float*       out = (float*)d_out;

    const int* src = ei;
    const int* dst = ei + N_EDGES;

    cudaFuncSetAttribute(k_gemm1_w, cudaFuncAttributeMaxDynamicSharedMemorySize, G1_SMEM);

    // degree + normalization
    k_zero_deg <<<(N_NODES + 255) / 256, 256>>>();
    k_count_deg<<<(N_EDGES + 255) / 256, 256>>>(dst);
    k_dinv     <<<(N_NODES + 255) / 256, 256>>>();

    // layer 1
    int gemm_blocks = (N_NODES + 127) / 128;            // 782
    k_gemm1_w <<<gemm_blocks, 256, G1_SMEM>>>(x, W1);
    k_scatter1<<<(N_EDGES * 32 + 255) / 256, 256>>>(src, dst);

    // layer 2
    k_gemm2_w <<<gemm_blocks, 256>>>(b1, W2, b2, out);
    k_scatter2<<<((N_EDGES / 2) * 32 + 255) / 256, 256>>>(src, dst, out);
}

// round 13
// speedup vs baseline: 1.5905x; 1.5026x over previous
#include <cuda_runtime.h>
#include <cuda_bf16.h>
#include <mma.h>
#include <cstdint>

using namespace nvcuda;

// Problem constants (fixed by the reference).
#define N_NODES 100000
#define N_EDGES 1600000
#define D_IN    256
#define D_HID   128
#define D_OUT   64
#define ADJ_CAP 128   // max in-degree bucket (deg ~ Binom mean 16; P(>64) ~ 1e-18)

// edge_index is int32 (JAX x64 disabled). tcgen05 unavailable (harness targets
// base sm_103) -> tensor path is wmma/HMMA.

// ---------------------------------------------------------------------------
// Scratch (static __device__ globals)
// g_hs   = h1 * dinv[row]     g_agg1 = aggregated layer-1 (init h1*dinv^2)
// g_hs2  = h2 * dinv[row]     g_adj  = per-dst src buckets, g_cnt = in-degree
// ---------------------------------------------------------------------------
__device__ __align__(16) float g_hs  [(size_t)N_NODES * D_HID];
__device__ __align__(16) float g_agg1[(size_t)N_NODES * D_HID];
__device__ __align__(16) float g_hs2 [(size_t)N_NODES * D_OUT];
__device__ int   g_adj [(size_t)N_NODES * ADJ_CAP];
__device__ int   g_cnt [N_NODES];
__device__ float g_dinv[N_NODES];

__device__ __forceinline__ void cvt_split(float v, __nv_bfloat16& h, __nv_bfloat16& l) {
    h = __float2bfloat16_rn(v);
    l = __float2bfloat16_rn(v - __bfloat162float(h));
}

// ---------------------------------------------------------------------------
// Bucket build + normalization
// ---------------------------------------------------------------------------
__global__ void k_zero_cnt() {
    int i = blockIdx.x * blockDim.x + threadIdx.x;
    if (i < N_NODES) g_cnt[i] = 0;
}
__global__ void k_fill(const int* __restrict__ src, const int* __restrict__ dst) {
    int e = blockIdx.x * blockDim.x + threadIdx.x;
    if (e >= N_EDGES) return;
    int d = dst[e];
    int p = atomicAdd(&g_cnt[d], 1);
    if (p < ADJ_CAP) g_adj[(size_t)d * ADJ_CAP + p] = src[e];
}
__global__ void k_dinv() {
    int i = blockIdx.x * blockDim.x + threadIdx.x;
    if (i < N_NODES) g_dinv[i] = rsqrtf(1.0f + (float)g_cnt[i]);
}

// ---------------------------------------------------------------------------
// GEMM1 (wmma bf16 3-term split, pipelined, 512 threads / 16 warps):
//   h = x @ W1 ; writes g_hs = h*dinv, g_agg1 = h*dinv^2
// 128x128 CTA tile, warp grid 4x4, warp tile 32x32 (2x2 m16n16k16 frags).
// K=256 in 8 chunks of 32, double-buffered smem + register prefetch.
// ---------------------------------------------------------------------------
#define G1_LDA 40
#define G1_LDB 136
#define G1_LDC 132
// per-buffer: Ah 10240 @0, Al 10240 @10240, Bh 8704 @20480, Bl 8704 @29184
#define G1_BUF  37888
#define G1_SMEM (2 * G1_BUF)     // 75776; epilogue Cs 128x132x4 = 67584 fits

__global__ __launch_bounds__(512) void k_gemm1_w(const float* __restrict__ x,
                                                 const float* __restrict__ W1) {
    extern __shared__ __align__(16) char smem[];

    const int t      = threadIdx.x;
    const int wid    = t >> 5;
    const int warp_m = wid >> 2;           // 0..3 (32-row band)
    const int warp_n = wid & 3;            // 0..3 (32-col band)
    const int block_row = blockIdx.x * 128;

    // A map: row = t>>2 (0..127), 8-float span (t&3)*8 within the 32-k chunk
    const int arow = t >> 2;
    const int acol = (t & 3) * 8;
    const int gr   = block_row + arow;
    const bool avalid = (gr < N_NODES);

    // B map: k-row = t>>4 (0..31), 8-float span (t&15)*8 of 128 cols
    const int bk = t >> 4;
    const int bn = (t & 15) * 8;

    const float4* xrow = (const float4*)(x + (size_t)gr * D_IN + acol);
    const float4* wrow = (const float4*)(W1 + (size_t)bk * D_HID + bn);

    wmma::fragment<wmma::accumulator, 16, 16, 16, float> acc[2][2];
#pragma unroll
    for (int mt = 0; mt < 2; mt++)
#pragma unroll
        for (int nt = 0; nt < 2; nt++) wmma::fill_fragment(acc[mt][nt], 0.0f);

    float4 ra[2], rb[2];

    auto load_chunk = [&](int c) {
        // A advance: 32 floats = 8 float4 per chunk within the row
#pragma unroll
        for (int i = 0; i < 2; i++)
            ra[i] = avalid ? xrow[c * 8 + i] : make_float4(0.f, 0.f, 0.f, 0.f);
        // B advance: 32 W1-rows = 32*(D_HID/4) = 1024 float4 per chunk
#pragma unroll
        for (int i = 0; i < 2; i++)
            rb[i] = wrow[(size_t)c * 32 * (D_HID / 4) + i];
    };
    auto store_chunk = [&](int b) {
        char* base = smem + b * G1_BUF;
        __nv_bfloat16 (*Ah)[G1_LDA] = (__nv_bfloat16(*)[G1_LDA])(base);
        __nv_bfloat16 (*Al)[G1_LDA] = (__nv_bfloat16(*)[G1_LDA])(base + 10240);
        __nv_bfloat16 (*Bh)[G1_LDB] = (__nv_bfloat16(*)[G1_LDB])(base + 20480);
        __nv_bfloat16 (*Bl)[G1_LDB] = (__nv_bfloat16(*)[G1_LDB])(base + 29184);
#pragma unroll
        for (int i = 0; i < 2; i++) {
            __nv_bfloat16 hx, hy, hz, hw, lx, ly, lz, lw;
            cvt_split(ra[i].x, hx, lx); cvt_split(ra[i].y, hy, ly);
            cvt_split(ra[i].z, hz, lz); cvt_split(ra[i].w, hw, lw);
            int kc = acol + i * 4;
            *(__nv_bfloat162*)&Ah[arow][kc]     = __nv_bfloat162(hx, hy);
            *(__nv_bfloat162*)&Ah[arow][kc + 2] = __nv_bfloat162(hz, hw);
            *(__nv_bfloat162*)&Al[arow][kc]     = __nv_bfloat162(lx, ly);
            *(__nv_bfloat162*)&Al[arow][kc + 2] = __nv_bfloat162(lz, lw);
        }
#pragma unroll
        for (int i = 0; i < 2; i++) {
            __nv_bfloat16 hx, hy, hz, hw, lx, ly, lz, lw;
            cvt_split(rb[i].x, hx, lx); cvt_split(rb[i].y, hy, ly);
            cvt_split(rb[i].z, hz, lz); cvt_split(rb[i].w, hw, lw);
            int nc = bn + i * 4;
            *(__nv_bfloat162*)&Bh[bk][nc]     = __nv_bfloat162(hx, hy);
            *(__nv_bfloat162*)&Bh[bk][nc + 2] = __nv_bfloat162(hz, hw);
            *(__nv_bfloat162*)&Bl[bk][nc]     = __nv_bfloat162(lx, ly);
            *(__nv_bfloat162*)&Bl[bk][nc + 2] = __nv_bfloat162(lz, lw);
        }
    };

    load_chunk(0);
    store_chunk(0);
    __syncthreads();

    for (int c = 0; c < D_IN / 32; c++) {
        if (c < D_IN / 32 - 1) load_chunk(c + 1);    // LDG issues early

        char* base = smem + (c & 1) * G1_BUF;
        __nv_bfloat16 (*Ah)[G1_LDA] = (__nv_bfloat16(*)[G1_LDA])(base);
        __nv_bfloat16 (*Al)[G1_LDA] = (__nv_bfloat16(*)[G1_LDA])(base + 10240);
        __nv_bfloat16 (*Bh)[G1_LDB] = (__nv_bfloat16(*)[G1_LDB])(base + 20480);
        __nv_bfloat16 (*Bl)[G1_LDB] = (__nv_bfloat16(*)[G1_LDB])(base + 29184);

#pragma unroll
        for (int ks = 0; ks < 32; ks += 16) {
            wmma::fragment<wmma::matrix_b, 16, 16, 16, __nv_bfloat16, wmma::row_major> fBh[2], fBl[2];
#pragma unroll
            for (int nt = 0; nt < 2; nt++) {
                int col = warp_n * 32 + nt * 16;
                wmma::load_matrix_sync(fBh[nt], &Bh[ks][col], G1_LDB);
                wmma::load_matrix_sync(fBl[nt], &Bl[ks][col], G1_LDB);
            }
#pragma unroll
            for (int mt = 0; mt < 2; mt++) {
                int row = warp_m * 32 + mt * 16;
                wmma::fragment<wmma::matrix_a, 16, 16, 16, __nv_bfloat16, wmma::row_major> fAh, fAl;
                wmma::load_matrix_sync(fAh, &Ah[row][ks], G1_LDA);
                wmma::load_matrix_sync(fAl, &Al[row][ks], G1_LDA);
#pragma unroll
                for (int nt = 0; nt < 2; nt++) {
                    wmma::mma_sync(acc[mt][nt], fAh, fBh[nt], acc[mt][nt]);
                    wmma::mma_sync(acc[mt][nt], fAh, fBl[nt], acc[mt][nt]);
                    wmma::mma_sync(acc[mt][nt], fAl, fBh[nt], acc[mt][nt]);
                }
            }
        }
        if (c < D_IN / 32 - 1) store_chunk((c + 1) & 1);
        __syncthreads();
    }

    // Epilogue: single pass — all 16 warps stage the full 128x128 into smem.
    float (*Cs)[G1_LDC] = (float(*)[G1_LDC])(smem);
#pragma unroll
    for (int mt = 0; mt < 2; mt++)
#pragma unroll
        for (int nt = 0; nt < 2; nt++)
            wmma::store_matrix_sync(&Cs[warp_m * 32 + mt * 16][warp_n * 32 + nt * 16],
                                    acc[mt][nt], G1_LDC, wmma::mem_row_major);
    __syncthreads();

    {
        int rr = t >> 2;                // 0..127
        int cq = (t & 3) * 32;
        int grow = block_row + rr;
        if (grow < N_NODES) {
            float di  = g_dinv[grow];
            float di2 = di * di;
            size_t base = (size_t)grow * D_HID + cq;
#pragma unroll
            for (int i = 0; i < 8; i++) {
                float4 v = *(float4*)&Cs[rr][cq + i * 4];
                *(float4*)(g_hs + base + i * 4) =
                    make_float4(v.x * di, v.y * di, v.z * di, v.w * di);
                *(float4*)(g_agg1 + base + i * 4) =
                    make_float4(v.x * di2, v.y * di2, v.z * di2, v.w * di2);
            }
        }
    }
}

// ---------------------------------------------------------------------------
// Pull layer 1: agg1[d] += (sum over src in adj[d]) hs[src] * dinv[d]
// One warp per dst node; lane owns float4 (128 floats). Register accumulate,
// single read-modify-write — no float atomics.
// ---------------------------------------------------------------------------
__global__ __launch_bounds__(256) void k_pull1() {
    int wid  = threadIdx.x >> 5;
    int lane = threadIdx.x & 31;
    int d    = blockIdx.x * 8 + wid;           // grid = 12500 * 8 = 100000 exact
    const int n = g_cnt[d];
    const int* __restrict__ adj = g_adj + (size_t)d * ADJ_CAP;
    const int co = lane * 4;

    float4 a0 = make_float4(0.f, 0.f, 0.f, 0.f);
    float4 a1 = make_float4(0.f, 0.f, 0.f, 0.f);
    int j = 0;
    for (; j + 1 < n; j += 2) {
        int s0 = adj[j], s1 = adj[j + 1];
        float4 v0 = *(const float4*)(g_hs + (size_t)s0 * D_HID + co);
        float4 v1 = *(const float4*)(g_hs + (size_t)s1 * D_HID + co);
        a0.x += v0.x; a0.y += v0.y; a0.z += v0.z; a0.w += v0.w;
        a1.x += v1.x; a1.y += v1.y; a1.z += v1.z; a1.w += v1.w;
    }
    if (j < n) {
        int s0 = adj[j];
        float4 v0 = *(const float4*)(g_hs + (size_t)s0 * D_HID + co);
        a0.x += v0.x; a0.y += v0.y; a0.z += v0.z; a0.w += v0.w;
    }
    float w = g_dinv[d];
    float* p = g_agg1 + (size_t)d * D_HID + co;
    float4 cur = *(float4*)p;
    *(float4*)p = make_float4(cur.x + (a0.x + a1.x) * w,
                              cur.y + (a0.y + a1.y) * w,
                              cur.z + (a0.z + a1.z) * w,
                              cur.w + (a0.w + a1.w) * w);
}

// ---------------------------------------------------------------------------
// GEMM2 (wmma bf16 3-term split): h2 = relu(agg1+b1) @ W2  (K=128, N=64)
// 128x64 CTA tile, 8 warps (4x2). Epilogue: g_hs2 = h2*dinv,
// out = h2*dinv^2 + b2 (pull2 then accumulates into out).
// ---------------------------------------------------------------------------
#define G2_LDA 40
#define G2_LDB 72
#define G2_LDC 68

__global__ __launch_bounds__(256) void k_gemm2_w(const float* __restrict__ b1,
                                                 const float* __restrict__ W2,
                                                 const float* __restrict__ b2,
                                                 float* __restrict__ out) {
    __shared__ __align__(16) union {
        struct {
            __nv_bfloat16 Ah[128][G2_LDA];
            __nv_bfloat16 Al[128][G2_LDA];
            __nv_bfloat16 Bh[32][G2_LDB];
            __nv_bfloat16 Bl[32][G2_LDB];
        } tiles;
        float Cs[128][G2_LDC];
    } sm;

    const int t      = threadIdx.x;
    const int wid    = t >> 5;
    const int warp_m = wid >> 1;
    const int warp_n = wid & 1;
    const int block_row = blockIdx.x * 128;

    const int arow = t >> 1;
    const int akq  = (t & 1) * 16;
    const int gr   = block_row + arow;
    const bool avalid = (gr < N_NODES);

    const int bk = t >> 3;
    const int bq = (t & 7) * 8;

    wmma::fragment<wmma::accumulator, 16, 16, 16, float> acc[2][2];
#pragma unroll
    for (int mt = 0; mt < 2; mt++)
#pragma unroll
        for (int nt = 0; nt < 2; nt++) wmma::fill_fragment(acc[mt][nt], 0.0f);

    for (int c = 0; c < D_HID / 32; c++) {
        const int k0 = c * 32;
        {
            const float4* ap = (const float4*)(g_agg1 + (size_t)gr * D_HID + k0 + akq);
            const float4* bp = (const float4*)(b1 + k0 + akq);
#pragma unroll
            for (int i = 0; i < 4; i++) {
                float4 v  = avalid ? ap[i] : make_float4(0.f, 0.f, 0.f, 0.f);
                float4 bb = bp[i];
                v.x = fmaxf(v.x + bb.x, 0.f); v.y = fmaxf(v.y + bb.y, 0.f);
                v.z = fmaxf(v.z + bb.z, 0.f); v.w = fmaxf(v.w + bb.w, 0.f);
                __nv_bfloat16 hx, hy, hz, hw, lx, ly, lz, lw;
                cvt_split(v.x, hx, lx); cvt_split(v.y, hy, ly);
                cvt_split(v.z, hz, lz); cvt_split(v.w, hw, lw);
                int kc = akq + i * 4;
                *(__nv_bfloat162*)&sm.tiles.Ah[arow][kc]     = __nv_bfloat162(hx, hy);
                *(__nv_bfloat162*)&sm.tiles.Ah[arow][kc + 2] = __nv_bfloat162(hz, hw);
                *(__nv_bfloat162*)&sm.tiles.Al[arow][kc]     = __nv_bfloat162(lx, ly);
                *(__nv_bfloat162*)&sm.tiles.Al[arow][kc + 2] = __nv_bfloat162(lz, lw);
            }
        }
        {
            const float4* wp = (const float4*)(W2 + (size_t)(k0 + bk) * D_OUT + bq);
#pragma unroll
            for (int i = 0; i < 2; i++) {
                float4 v = wp[i];
                __nv_bfloat16 hx, hy, hz, hw, lx, ly, lz, lw;
                cvt_split(v.x, hx, lx); cvt_split(v.y, hy, ly);
                cvt_split(v.z, hz, lz); cvt_split(v.w, hw, lw);
                int nc = bq + i * 4;
                *(__nv_bfloat162*)&sm.tiles.Bh[bk][nc]     = __nv_bfloat162(hx, hy);
                *(__nv_bfloat162*)&sm.tiles.Bh[bk][nc + 2] = __nv_bfloat162(hz, hw);
                *(__nv_bfloat162*)&sm.tiles.Bl[bk][nc]     = __nv_bfloat162(lx, ly);
                *(__nv_bfloat162*)&sm.tiles.Bl[bk][nc + 2] = __nv_bfloat162(lz, lw);
            }
        }
        __syncthreads();

#pragma unroll
        for (int ks = 0; ks < 32; ks += 16) {
            wmma::fragment<wmma::matrix_b, 16, 16, 16, __nv_bfloat16, wmma::row_major> fBh[2], fBl[2];
#pragma unroll
            for (int nt = 0; nt < 2; nt++) {
                int col = warp_n * 32 + nt * 16;
                wmma::load_matrix_sync(fBh[nt], &sm.tiles.Bh[ks][col], G2_LDB);
                wmma::load_matrix_sync(fBl[nt], &sm.tiles.Bl[ks][col], G2_LDB);
            }
#pragma unroll
            for (int mt = 0; mt < 2; mt++) {
                int row = warp_m * 32 + mt * 16;
                wmma::fragment<wmma::matrix_a, 16, 16, 16, __nv_bfloat16, wmma::row_major> fAh, fAl;
                wmma::load_matrix_sync(fAh, &sm.tiles.Ah[row][ks], G2_LDA);
                wmma::load_matrix_sync(fAl, &sm.tiles.Al[row][ks], G2_LDA);
#pragma unroll
                for (int nt = 0; nt < 2; nt++) {
                    wmma::mma_sync(acc[mt][nt], fAh, fBh[nt], acc[mt][nt]);
                    wmma::mma_sync(acc[mt][nt], fAh, fBl[nt], acc[mt][nt]);
                    wmma::mma_sync(acc[mt][nt], fAl, fBh[nt], acc[mt][nt]);
                }
            }
        }
        __syncthreads();
    }

#pragma unroll
    for (int mt = 0; mt < 2; mt++)
#pragma unroll
        for (int nt = 0; nt < 2; nt++)
            wmma::store_matrix_sync(&sm.Cs[warp_m * 32 + mt * 16][warp_n * 32 + nt * 16],
                                    acc[mt][nt], G2_LDC, wmma::mem_row_major);
    __syncthreads();

    int rr = t >> 1;
    int ch = (t & 1) * 32;
    int grow = block_row + rr;
    if (grow < N_NODES) {
        float di  = g_dinv[grow];
        float di2 = di * di;
        size_t base = (size_t)grow * D_OUT + ch;
#pragma unroll
        for (int i = 0; i < 8; i++) {
            float4 v  = *(float4*)&sm.Cs[rr][ch + i * 4];
            float4 bb = *(const float4*)(b2 + ch + i * 4);
            *(float4*)(g_hs2 + base + i * 4) =
                make_float4(v.x * di, v.y * di, v.z * di, v.w * di);
            *(float4*)(out + base + i * 4) =
                make_float4(v.x * di2 + bb.x, v.y * di2 + bb.y,
                            v.z * di2 + bb.z, v.w * di2 + bb.w);
        }
    }
}

// ---------------------------------------------------------------------------
// Pull layer 2: out[d] += (sum over src) hs2[src] * dinv[d]
// One warp per dst node; lane owns float2 (64 floats).
// ---------------------------------------------------------------------------
__global__ __launch_bounds__(256) void k_pull2(float* __restrict__ out) {
    int wid  = threadIdx.x >> 5;
    int lane = threadIdx.x & 31;
    int d    = blockIdx.x * 8 + wid;
    const int n = g_cnt[d];
    const int* __restrict__ adj = g_adj + (size_t)d * ADJ_CAP;
    const int co = lane * 2;

    float2 a0 = make_float2(0.f, 0.f);
    float2 a1 = make_float2(0.f, 0.f);
    int j = 0;
    for (; j + 1 < n; j += 2) {
        int s0 = adj[j], s1 = adj[j + 1];
        float2 v0 = *(const float2*)(g_hs2 + (size_t)s0 * D_OUT + co);
        float2 v1 = *(const float2*)(g_hs2 + (size_t)s1 * D_OUT + co);
        a0.x += v0.x; a0.y += v0.y;
        a1.x += v1.x; a1.y += v1.y;
    }
    if (j < n) {
        int s0 = adj[j];
        float2 v0 = *(const float2*)(g_hs2 + (size_t)s0 * D_OUT + co);
        a0.x += v0.x; a0.y += v0.y;
    }
    float w = g_dinv[d];
    float* p = out + (size_t)d * D_OUT + co;
    float2 cur = *(float2*)p;
    *(float2*)p = make_float2(cur.x + (a0.x + a1.x) * w,
                              cur.y + (a0.y + a1.y) * w);
}

// ---------------------------------------------------------------------------
// Launch sequence (graph-capturable: kernel launches only)
// ---------------------------------------------------------------------------
extern "C" void kernel_launch(void* const* d_in, const int* in_sizes, int n_in,
                              void* d_out, int out_size) {
    const float* x   = (const float*)d_in[0];
    const int*   ei  = (const int*)d_in[1];   // [2, E] int32
    const float* W1  = (const float*)d_in[2];
    const float* b1  = (const float*)d_in[3];
    const float* W2  = (const float*)d_in[4];
    const float* b2  = (const float*)d_in[5];
    float*       out = (float*)d_out;

    const int* src = ei;
    const int* dst = ei + N_EDGES;

    cudaFuncSetAttribute(k_gemm1_w, cudaFuncAttributeMaxDynamicSharedMemorySize, G1_SMEM);

    // adjacency buckets (also produces degree) + normalization
    k_zero_cnt<<<(N_NODES + 255) / 256, 256>>>();
    k_fill    <<<(N_EDGES + 255) / 256, 256>>>(src, dst);
    k_dinv    <<<(N_NODES + 255) / 256, 256>>>();

    // layer 1
    int gemm_blocks = (N_NODES + 127) / 128;            // 782
    k_gemm1_w<<<gemm_blocks, 512, G1_SMEM>>>(x, W1);
    k_pull1  <<<N_NODES / 8, 256>>>();                  // 12500 blocks, warp/node

    // layer 2
    k_gemm2_w<<<gemm_blocks, 256>>>(b1, W2, b2, out);
    k_pull2  <<<N_NODES / 8, 256>>>(out);
}

// round 16
// speedup vs baseline: 1.6757x; 1.0536x over previous
#include <cuda_runtime.h>
#include <cuda_bf16.h>
#include <mma.h>
#include <cstdint>

using namespace nvcuda;

// Problem constants (fixed by the reference).
#define N_NODES 100000
#define N_EDGES 1600000
#define D_IN    256
#define D_HID   128
#define D_OUT   64
#define ADJ_CAP 128   // max in-degree bucket (deg ~ Binom mean 16; P(>64) ~ 1e-18)

// edge_index is int32 (JAX x64 disabled). tcgen05 unavailable (harness targets
// base sm_103) -> tensor path is wmma/HMMA.
// R14/R15 failed with "GB300 container failed twice" — a driver-side
// acquisition RuntimeError (same string as R4 on the EMPTY stub), not a
// kernel failure. Third submission of the same kernel; content unchanged.

// ---------------------------------------------------------------------------
// Scratch (static __device__ globals)
// g_h   = x @ W1 (unscaled)   g_agg1 = layer-1 aggregate (pull1 writes whole)
// g_hs2 = h2 * dinv[row]      g_adj  = per-dst src buckets, g_cnt = in-degree
// ---------------------------------------------------------------------------
__device__ __align__(16) float g_h   [(size_t)N_NODES * D_HID];
__device__ __align__(16) float g_agg1[(size_t)N_NODES * D_HID];
__device__ __align__(16) float g_hs2 [(size_t)N_NODES * D_OUT];
__device__ int   g_adj [(size_t)N_NODES * ADJ_CAP];
__device__ int   g_cnt [N_NODES];
__device__ float g_dinv[N_NODES];

__device__ __forceinline__ void cvt_split(float v, __nv_bfloat16& h, __nv_bfloat16& l) {
    h = __float2bfloat16_rn(v);
    l = __float2bfloat16_rn(v - __bfloat162float(h));
}

// ---------------------------------------------------------------------------
// Bucket build + normalization
// ---------------------------------------------------------------------------
__global__ void k_zero_cnt() {
    int i = blockIdx.x * blockDim.x + threadIdx.x;
    if (i < N_NODES) g_cnt[i] = 0;
}
__global__ void k_fill(const int* __restrict__ src, const int* __restrict__ dst) {
    int e = blockIdx.x * blockDim.x + threadIdx.x;
    if (e >= N_EDGES) return;
    int d = dst[e];
    int p = atomicAdd(&g_cnt[d], 1);
    if (p < ADJ_CAP) g_adj[(size_t)d * ADJ_CAP + p] = src[e];
}
__global__ void k_dinv() {
    int i = blockIdx.x * blockDim.x + threadIdx.x;
    if (i < N_NODES) g_dinv[i] = rsqrtf(1.0f + (float)g_cnt[i]);
}

// ---------------------------------------------------------------------------
// GEMM1 (wmma bf16 3-term split, pipelined, 2 CTAs/SM):
//   g_h = x @ W1   (unscaled; pull1 applies all dinv factors)
// 64x128 CTA tile, 256 threads, warp grid 2x4, warp tile 32x32 (2x2 frags).
// K=256 in 8 chunks of 32, double-buffered smem + register prefetch.
// 2 independent CTAs per SM -> barriers interleave, latency hidden.
// ---------------------------------------------------------------------------
#define H1_ROWS 64
#define G1_LDA 40
#define G1_LDB 136
#define G1_LDC 132
// per-buffer: Ah 5120 @0, Al 5120 @5120, Bh 8704 @10240, Bl 8704 @18944
#define G1_BUF  27648
#define G1_SMEM (2 * G1_BUF)   // 55296; epilogue Cs 64x132x4 = 33792 fits

__global__ __launch_bounds__(256, 2) void k_gemm1_w(const float* __restrict__ x,
                                                    const float* __restrict__ W1) {
    extern __shared__ __align__(16) char smem[];

    const int t      = threadIdx.x;
    const int wid    = t >> 5;
    const int warp_m = wid >> 2;           // 0..1 (32-row band)
    const int warp_n = wid & 3;            // 0..3 (32-col band)
    const int block_row = blockIdx.x * H1_ROWS;

    // A map: row = t>>2 (0..63), 8-float span (t&3)*8 within the 32-k chunk
    const int arow = t >> 2;
    const int acol = (t & 3) * 8;
    const int gr   = block_row + arow;
    const bool avalid = (gr < N_NODES);

    // B map: k-row = t>>3 (0..31), 16-float span (t&7)*16 of 128 cols
    const int bk = t >> 3;
    const int bn = (t & 7) * 16;

    const float4* xrow = (const float4*)(x + (size_t)gr * D_IN + acol);
    const float4* wrow = (const float4*)(W1 + (size_t)bk * D_HID + bn);

    wmma::fragment<wmma::accumulator, 16, 16, 16, float> acc[2][2];
#pragma unroll
    for (int mt = 0; mt < 2; mt++)
#pragma unroll
        for (int nt = 0; nt < 2; nt++) wmma::fill_fragment(acc[mt][nt], 0.0f);

    float4 ra[2], rb[4];

    auto load_chunk = [&](int c) {
        // A advance: 32 floats = 8 float4 per chunk within the row
#pragma unroll
        for (int i = 0; i < 2; i++)
            ra[i] = avalid ? xrow[c * 8 + i] : make_float4(0.f, 0.f, 0.f, 0.f);
        // B advance: 32 W1-rows = 32*(D_HID/4) float4 per chunk
#pragma unroll
        for (int i = 0; i < 4; i++)
            rb[i] = wrow[(size_t)c * 32 * (D_HID / 4) + i];
    };
    auto store_chunk = [&](int b) {
        char* base = smem + b * G1_BUF;
        __nv_bfloat16 (*Ah)[G1_LDA] = (__nv_bfloat16(*)[G1_LDA])(base);
        __nv_bfloat16 (*Al)[G1_LDA] = (__nv_bfloat16(*)[G1_LDA])(base + 5120);
        __nv_bfloat16 (*Bh)[G1_LDB] = (__nv_bfloat16(*)[G1_LDB])(base + 10240);
        __nv_bfloat16 (*Bl)[G1_LDB] = (__nv_bfloat16(*)[G1_LDB])(base + 18944);
#pragma unroll
        for (int i = 0; i < 2; i++) {
            __nv_bfloat16 hx, hy, hz, hw, lx, ly, lz, lw;
            cvt_split(ra[i].x, hx, lx); cvt_split(ra[i].y, hy, ly);
            cvt_split(ra[i].z, hz, lz); cvt_split(ra[i].w, hw, lw);
            int kc = acol + i * 4;
            *(__nv_bfloat162*)&Ah[arow][kc]     = __nv_bfloat162(hx, hy);
            *(__nv_bfloat162*)&Ah[arow][kc + 2] = __nv_bfloat162(hz, hw);
            *(__nv_bfloat162*)&Al[arow][kc]     = __nv_bfloat162(lx, ly);
            *(__nv_bfloat162*)&Al[arow][kc + 2] = __nv_bfloat162(lz, lw);
        }
#pragma unroll
        for (int i = 0; i < 4; i++) {
            __nv_bfloat16 hx, hy, hz, hw, lx, ly, lz, lw;
            cvt_split(rb[i].x, hx, lx); cvt_split(rb[i].y, hy, ly);
            cvt_split(rb[i].z, hz, lz); cvt_split(rb[i].w, hw, lw);
            int nc = bn + i * 4;
            *(__nv_bfloat162*)&Bh[bk][nc]     = __nv_bfloat162(hx, hy);
            *(__nv_bfloat162*)&Bh[bk][nc + 2] = __nv_bfloat162(hz, hw);
            *(__nv_bfloat162*)&Bl[bk][nc]     = __nv_bfloat162(lx, ly);
            *(__nv_bfloat162*)&Bl[bk][nc + 2] = __nv_bfloat162(lz, lw);
        }
    };

    load_chunk(0);
    store_chunk(0);
    __syncthreads();

    for (int c = 0; c < D_IN / 32; c++) {
        if (c < D_IN / 32 - 1) load_chunk(c + 1);    // LDG issues early

        char* base = smem + (c & 1) * G1_BUF;
        __nv_bfloat16 (*Ah)[G1_LDA] = (__nv_bfloat16(*)[G1_LDA])(base);
        __nv_bfloat16 (*Al)[G1_LDA] = (__nv_bfloat16(*)[G1_LDA])(base + 5120);
        __nv_bfloat16 (*Bh)[G1_LDB] = (__nv_bfloat16(*)[G1_LDB])(base + 10240);
        __nv_bfloat16 (*Bl)[G1_LDB] = (__nv_bfloat16(*)[G1_LDB])(base + 18944);

#pragma unroll
        for (int ks = 0; ks < 32; ks += 16) {
            wmma::fragment<wmma::matrix_b, 16, 16, 16, __nv_bfloat16, wmma::row_major> fBh[2], fBl[2];
#pragma unroll
            for (int nt = 0; nt < 2; nt++) {
                int col = warp_n * 32 + nt * 16;
                wmma::load_matrix_sync(fBh[nt], &Bh[ks][col], G1_LDB);
                wmma::load_matrix_sync(fBl[nt], &Bl[ks][col], G1_LDB);
            }
#pragma unroll
            for (int mt = 0; mt < 2; mt++) {
                int row = warp_m * 32 + mt * 16;
                wmma::fragment<wmma::matrix_a, 16, 16, 16, __nv_bfloat16, wmma::row_major> fAh, fAl;
                wmma::load_matrix_sync(fAh, &Ah[row][ks], G1_LDA);
                wmma::load_matrix_sync(fAl, &Al[row][ks], G1_LDA);
#pragma unroll
                for (int nt = 0; nt < 2; nt++) {
                    wmma::mma_sync(acc[mt][nt], fAh, fBh[nt], acc[mt][nt]);
                    wmma::mma_sync(acc[mt][nt], fAh, fBl[nt], acc[mt][nt]);
                    wmma::mma_sync(acc[mt][nt], fAl, fBh[nt], acc[mt][nt]);
                }
            }
        }
        if (c < D_IN / 32 - 1) store_chunk((c + 1) & 1);
        __syncthreads();
    }

    // Epilogue: stage 64x128 fp32 in smem, write g_h only (no dinv needed).
    float (*Cs)[G1_LDC] = (float(*)[G1_LDC])(smem);
#pragma unroll
    for (int mt = 0; mt < 2; mt++)
#pragma unroll
        for (int nt = 0; nt < 2; nt++)
            wmma::store_matrix_sync(&Cs[warp_m * 32 + mt * 16][warp_n * 32 + nt * 16],
                                    acc[mt][nt], G1_LDC, wmma::mem_row_major);
    __syncthreads();

    {
        int rr = t >> 2;                // 0..63
        int cq = (t & 3) * 32;
        int grow = block_row + rr;
        if (grow < N_NODES) {
            size_t base = (size_t)grow * D_HID + cq;
#pragma unroll
            for (int i = 0; i < 8; i++)
                *(float4*)(g_h + base + i * 4) = *(float4*)&Cs[rr][cq + i * 4];
        }
    }
}

// ---------------------------------------------------------------------------
// Pull layer 1 (fully fused, pure store):
//   agg1[d] = dinv[d] * sum_j h[adj[d][j]] * dinv[adj[d][j]] + h[d]*dinv[d]^2
// One warp per dst node; lane owns float4 (128 floats). No atomics, no RMW.
// ---------------------------------------------------------------------------
__global__ __launch_bounds__(256) void k_pull1() {
    int wid  = threadIdx.x >> 5;
    int lane = threadIdx.x & 31;
    int d    = blockIdx.x * 8 + wid;           // grid = 12500 * 8 = 100000 exact
    const int n = g_cnt[d];
    const int* __restrict__ adj = g_adj + (size_t)d * ADJ_CAP;
    const int co = lane * 4;

    float4 a0 = make_float4(0.f, 0.f, 0.f, 0.f);
    float4 a1 = make_float4(0.f, 0.f, 0.f, 0.f);
    int j = 0;
    for (; j + 1 < n; j += 2) {
        int s0 = adj[j], s1 = adj[j + 1];
        float w0 = g_dinv[s0], w1 = g_dinv[s1];
        float4 v0 = *(const float4*)(g_h + (size_t)s0 * D_HID + co);
        float4 v1 = *(const float4*)(g_h + (size_t)s1 * D_HID + co);
        a0.x += v0.x * w0; a0.y += v0.y * w0; a0.z += v0.z * w0; a0.w += v0.w * w0;
        a1.x += v1.x * w1; a1.y += v1.y * w1; a1.z += v1.z * w1; a1.w += v1.w * w1;
    }
    if (j < n) {
        int s0 = adj[j];
        float w0 = g_dinv[s0];
        float4 v0 = *(const float4*)(g_h + (size_t)s0 * D_HID + co);
        a0.x += v0.x * w0; a0.y += v0.y * w0; a0.z += v0.z * w0; a0.w += v0.w * w0;
    }
    float wd  = g_dinv[d];
    float wd2 = wd * wd;
    float4 hd = *(const float4*)(g_h + (size_t)d * D_HID + co);
    *(float4*)(g_agg1 + (size_t)d * D_HID + co) =
        make_float4(wd * (a0.x + a1.x) + hd.x * wd2,
                    wd * (a0.y + a1.y) + hd.y * wd2,
                    wd * (a0.z + a1.z) + hd.z * wd2,
                    wd * (a0.w + a1.w) + hd.w * wd2);
}

// ---------------------------------------------------------------------------
// GEMM2 (wmma bf16 3-term split): h2 = relu(agg1+b1) @ W2  (K=128, N=64)
// 128x64 CTA tile, 8 warps (4x2). Epilogue: g_hs2 = h2*dinv,
// out = h2*dinv^2 + b2 (pull2 then accumulates into out).
// ---------------------------------------------------------------------------
#define G2_LDA 40
#define G2_LDB 72
#define G2_LDC 68

__global__ __launch_bounds__(256) void k_gemm2_w(const float* __restrict__ b1,
                                                 const float* __restrict__ W2,
                                                 const float* __restrict__ b2,
                                                 float* __restrict__ out) {
    __shared__ __align__(16) union {
        struct {
            __nv_bfloat16 Ah[128][G2_LDA];
            __nv_bfloat16 Al[128][G2_LDA];
            __nv_bfloat16 Bh[32][G2_LDB];
            __nv_bfloat16 Bl[32][G2_LDB];
        } tiles;
        float Cs[128][G2_LDC];
    } sm;

    const int t      = threadIdx.x;
    const int wid    = t >> 5;
    const int warp_m = wid >> 1;
    const int warp_n = wid & 1;
    const int block_row = blockIdx.x * 128;

    const int arow = t >> 1;
    const int akq  = (t & 1) * 16;
    const int gr   = block_row + arow;
    const bool avalid = (gr < N_NODES);

    const int bk = t >> 3;
    const int bq = (t & 7) * 8;

    wmma::fragment<wmma::accumulator, 16, 16, 16, float> acc[2][2];
#pragma unroll
    for (int mt = 0; mt < 2; mt++)
#pragma unroll
        for (int nt = 0; nt < 2; nt++) wmma::fill_fragment(acc[mt][nt], 0.0f);

    for (int c = 0; c < D_HID / 32; c++) {
        const int k0 = c * 32;
        {
            const float4* ap = (const float4*)(g_agg1 + (size_t)gr * D_HID + k0 + akq);
            const float4* bp = (const float4*)(b1 + k0 + akq);
#pragma unroll
            for (int i = 0; i < 4; i++) {
                float4 v  = avalid ? ap[i] : make_float4(0.f, 0.f, 0.f, 0.f);
                float4 bb = bp[i];
                v.x = fmaxf(v.x + bb.x, 0.f); v.y = fmaxf(v.y + bb.y, 0.f);
                v.z = fmaxf(v.z + bb.z, 0.f); v.w = fmaxf(v.w + bb.w, 0.f);
                __nv_bfloat16 hx, hy, hz, hw, lx, ly, lz, lw;
                cvt_split(v.x, hx, lx); cvt_split(v.y, hy, ly);
                cvt_split(v.z, hz, lz); cvt_split(v.w, hw, lw);
                int kc = akq + i * 4;
                *(__nv_bfloat162*)&sm.tiles.Ah[arow][kc]     = __nv_bfloat162(hx, hy);
                *(__nv_bfloat162*)&sm.tiles.Ah[arow][kc + 2] = __nv_bfloat162(hz, hw);
                *(__nv_bfloat162*)&sm.tiles.Al[arow][kc]     = __nv_bfloat162(lx, ly);
                *(__nv_bfloat162*)&sm.tiles.Al[arow][kc + 2] = __nv_bfloat162(lz, lw);
            }
        }
        {
            const float4* wp = (const float4*)(W2 + (size_t)(k0 + bk) * D_OUT + bq);
#pragma unroll
            for (int i = 0; i < 2; i++) {
                float4 v = wp[i];
                __nv_bfloat16 hx, hy, hz, hw, lx, ly, lz, lw;
                cvt_split(v.x, hx, lx); cvt_split(v.y, hy, ly);
                cvt_split(v.z, hz, lz); cvt_split(v.w, hw, lw);
                int nc = bq + i * 4;
                *(__nv_bfloat162*)&sm.tiles.Bh[bk][nc]     = __nv_bfloat162(hx, hy);
                *(__nv_bfloat162*)&sm.tiles.Bh[bk][nc + 2] = __nv_bfloat162(hz, hw);
                *(__nv_bfloat162*)&sm.tiles.Bl[bk][nc]     = __nv_bfloat162(lx, ly);
                *(__nv_bfloat162*)&sm.tiles.Bl[bk][nc + 2] = __nv_bfloat162(lz, lw);
            }
        }
        __syncthreads();

#pragma unroll
        for (int ks = 0; ks < 32; ks += 16) {
            wmma::fragment<wmma::matrix_b, 16, 16, 16, __nv_bfloat16, wmma::row_major> fBh[2], fBl[2];
#pragma unroll
            for (int nt = 0; nt < 2; nt++) {
                int col = warp_n * 32 + nt * 16;
                wmma::load_matrix_sync(fBh[nt], &sm.tiles.Bh[ks][col], G2_LDB);
                wmma::load_matrix_sync(fBl[nt], &sm.tiles.Bl[ks][col], G2_LDB);
            }
#pragma unroll
            for (int mt = 0; mt < 2; mt++) {
                int row = warp_m * 32 + mt * 16;
                wmma::fragment<wmma::matrix_a, 16, 16, 16, __nv_bfloat16, wmma::row_major> fAh, fAl;
                wmma::load_matrix_sync(fAh, &sm.tiles.Ah[row][ks], G2_LDA);
                wmma::load_matrix_sync(fAl, &sm.tiles.Al[row][ks], G2_LDA);
#pragma unroll
                for (int nt = 0; nt < 2; nt++) {
                    wmma::mma_sync(acc[mt][nt], fAh, fBh[nt], acc[mt][nt]);
                    wmma::mma_sync(acc[mt][nt], fAh, fBl[nt], acc[mt][nt]);
                    wmma::mma_sync(acc[mt][nt], fAl, fBh[nt], acc[mt][nt]);
                }
            }
        }
        __syncthreads();
    }

#pragma unroll
    for (int mt = 0; mt < 2; mt++)
#pragma unroll
        for (int nt = 0; nt < 2; nt++)
            wmma::store_matrix_sync(&sm.Cs[warp_m * 32 + mt * 16][warp_n * 32 + nt * 16],
                                    acc[mt][nt], G2_LDC, wmma::mem_row_major);
    __syncthreads();

    int rr = t >> 1;
    int ch = (t & 1) * 32;
    int grow = block_row + rr;
    if (grow < N_NODES) {
        float di  = g_dinv[grow];
        float di2 = di * di;
        size_t base = (size_t)grow * D_OUT + ch;
#pragma unroll
        for (int i = 0; i < 8; i++) {
            float4 v  = *(float4*)&sm.Cs[rr][ch + i * 4];
            float4 bb = *(const float4*)(b2 + ch + i * 4);
            *(float4*)(g_hs2 + base + i * 4) =
                make_float4(v.x * di, v.y * di, v.z * di, v.w * di);
            *(float4*)(out + base + i * 4) =
                make_float4(v.x * di2 + bb.x, v.y * di2 + bb.y,
                            v.z * di2 + bb.z, v.w * di2 + bb.w);
        }
    }
}

// ---------------------------------------------------------------------------
// Pull layer 2: out[d] += dinv[d] * sum hs2[adj[d][j]]  (hs2 pre-scaled)
// One warp per dst node; lane owns float2 (64 floats).
// ---------------------------------------------------------------------------
__global__ __launch_bounds__(256) void k_pull2(float* __restrict__ out) {
    int wid  = threadIdx.x >> 5;
    int lane = threadIdx.x & 31;
    int d    = blockIdx.x * 8 + wid;
    const int n = g_cnt[d];
    const int* __restrict__ adj = g_adj + (size_t)d * ADJ_CAP;
    const int co = lane * 2;

    float2 a0 = make_float2(0.f, 0.f);
    float2 a1 = make_float2(0.f, 0.f);
    int j = 0;
    for (; j + 1 < n; j += 2) {
        int s0 = adj[j], s1 = adj[j + 1];
        float2 v0 = *(const float2*)(g_hs2 + (size_t)s0 * D_OUT + co);
        float2 v1 = *(const float2*)(g_hs2 + (size_t)s1 * D_OUT + co);
        a0.x += v0.x; a0.y += v0.y;
        a1.x += v1.x; a1.y += v1.y;
    }
    if (j < n) {
        int s0 = adj[j];
        float2 v0 = *(const float2*)(g_hs2 + (size_t)s0 * D_OUT + co);
        a0.x += v0.x; a0.y += v0.y;
    }
    float w = g_dinv[d];
    float* p = out + (size_t)d * D_OUT + co;
    float2 cur = *(float2*)p;
    *(float2*)p = make_float2(cur.x + (a0.x + a1.x) * w,
                              cur.y + (a0.y + a1.y) * w);
}

// ---------------------------------------------------------------------------
// Launch sequence (graph-capturable: kernel launches only)
// ---------------------------------------------------------------------------
extern "C" void kernel_launch(void* const* d_in, const int* in_sizes, int n_in,
                              void* d_out, int out_size) {
    const float* x   = (const float*)d_in[0];
    const int*   ei  = (const int*)d_in[1];   // [2, E] int32
    const float* W1  = (const float*)d_in[2];
    const float* b1  = (const float*)d_in[3];
    const float* W2  = (const float*)d_in[4];
    const float* b2  = (const float*)d_in[5];
    float*       out = (float*)d_out;

    const int* src = ei;
    const int* dst = ei + N_EDGES;

    cudaFuncSetAttribute(k_gemm1_w, cudaFuncAttributeMaxDynamicSharedMemorySize, G1_SMEM);

    // adjacency buckets (also produces degree) + normalization
    k_zero_cnt<<<(N_NODES + 255) / 256, 256>>>();
    k_fill    <<<(N_EDGES + 255) / 256, 256>>>(src, dst);
    k_dinv    <<<(N_NODES + 255) / 256, 256>>>();

    // layer 1
    k_gemm1_w<<<(N_NODES + H1_ROWS - 1) / H1_ROWS, 256, G1_SMEM>>>(x, W1);  // 1563 CTAs
    k_pull1  <<<N_NODES / 8, 256>>>();                                      // warp/node

    // layer 2
    k_gemm2_w<<<(N_NODES + 127) / 128, 256>>>(b1, W2, b2, out);
    k_pull2  <<<N_NODES / 8, 256>>>(out);
}

// round 17
// speedup vs baseline: 1.7199x; 1.0264x over previous
#include <cuda_runtime.h>
#include <cuda_bf16.h>
#include <mma.h>
#include <cstdint>

using namespace nvcuda;

// Problem constants (fixed by the reference).
#define N_NODES 100000
#define N_EDGES 1600000
#define D_IN    256
#define D_HID   128
#define D_OUT   64
#define ADJ_CAP 128   // max in-degree bucket (deg ~ Binom mean 16; P(>64) ~ 1e-18)

// edge_index is int32 (JAX x64 disabled). tcgen05 unavailable (harness targets
// base sm_103) -> tensor path is wmma/HMMA.

// ---------------------------------------------------------------------------
// Scratch (static __device__ globals)
// ---------------------------------------------------------------------------
__device__ __align__(16) float g_h   [(size_t)N_NODES * D_HID];
__device__ __align__(16) float g_agg1[(size_t)N_NODES * D_HID];
__device__ __align__(16) float g_hs2 [(size_t)N_NODES * D_OUT];
__device__ __align__(16) __nv_bfloat16 g_w1h[D_IN * D_HID];  // W1 hi (bf16)
__device__ __align__(16) __nv_bfloat16 g_w1l[D_IN * D_HID];  // W1 lo residual
__device__ int   g_adj [(size_t)N_NODES * ADJ_CAP];
__device__ int   g_cnt [N_NODES];
__device__ float g_dinv[N_NODES];

__device__ __forceinline__ void cvt_split(float v, __nv_bfloat16& h, __nv_bfloat16& l) {
    h = __float2bfloat16_rn(v);
    l = __float2bfloat16_rn(v - __bfloat162float(h));
}

// ---------------------------------------------------------------------------
// Prep: W1 -> bf16 hi/lo (done once per launch; 32768 elems)
// ---------------------------------------------------------------------------
__global__ void k_w1cvt(const float* __restrict__ W1) {
    int i = blockIdx.x * blockDim.x + threadIdx.x;
    if (i < D_IN * D_HID) {
        __nv_bfloat16 h, l;
        cvt_split(W1[i], h, l);
        g_w1h[i] = h;
        g_w1l[i] = l;
    }
}

// ---------------------------------------------------------------------------
// Bucket build + normalization
// ---------------------------------------------------------------------------
__global__ void k_zero_cnt() {
    int i = blockIdx.x * blockDim.x + threadIdx.x;
    if (i < N_NODES) g_cnt[i] = 0;
}
__global__ void k_fill(const int* __restrict__ src, const int* __restrict__ dst) {
    int e = blockIdx.x * blockDim.x + threadIdx.x;
    if (e >= N_EDGES) return;
    int d = dst[e];
    int p = atomicAdd(&g_cnt[d], 1);
    if (p < ADJ_CAP) g_adj[(size_t)d * ADJ_CAP + p] = src[e];
}
__global__ void k_dinv() {
    int i = blockIdx.x * blockDim.x + threadIdx.x;
    if (i < N_NODES) g_dinv[i] = rsqrtf(1.0f + (float)g_cnt[i]);
}

// ---------------------------------------------------------------------------
// GEMM1 (wmma bf16 3-term split, persistent, 2 CTAs/SM):
//   g_h = x @ W1   (unscaled; pull1 applies all dinv factors)
// 64x128 tile, 256 threads, warp grid 2x4, warp tile 32x32 (2x2 frags).
// K=256 in 8 chunks of 32, double-buffered smem + register prefetch.
// B tiles are pure uint4 copies of precomputed g_w1h/g_w1l (no conversion).
// Persistent grid (2 x #SM) strides over tiles -> flat tail.
// ---------------------------------------------------------------------------
#define H1_ROWS 64
#define G1_NT   ((N_NODES + H1_ROWS - 1) / H1_ROWS)   // 1563 tiles
#define G1_LDA 40
#define G1_LDB 136
#define G1_LDC 132
// per-buffer: Ah 5120 @0, Al 5120 @5120, Bh 8704 @10240, Bl 8704 @18944
#define G1_BUF  27648
#define G1_SMEM (2 * G1_BUF)   // 55296; epilogue Cs 64x132x4 = 33792 fits

__global__ __launch_bounds__(256, 2) void k_gemm1_w(const float* __restrict__ x) {
    extern __shared__ __align__(16) char smem[];

    const int t      = threadIdx.x;
    const int wid    = t >> 5;
    const int warp_m = wid >> 2;           // 0..1 (32-row band)
    const int warp_n = wid & 3;            // 0..3 (32-col band)

    // A map: row = t>>2 (0..63), 8-float span (t&3)*8 within the 32-k chunk
    const int arow = t >> 2;
    const int acol = (t & 3) * 8;

    // B map: pure copy, 2 uint4 (= 8 bf16) per thread per array per chunk.
    // idx = t*2 + i ; row = idx>>4 (0..31), col = (idx&15)*8 of 128.
    const int bi0 = t * 2, bi1 = t * 2 + 1;
    const int br0 = bi0 >> 4, bc0 = (bi0 & 15) * 8;
    const int br1 = bi1 >> 4, bc1 = (bi1 & 15) * 8;
    const uint4* w1h4 = (const uint4*)g_w1h;   // 16 uint4 per 128-col row
    const uint4* w1l4 = (const uint4*)g_w1l;

    wmma::fragment<wmma::accumulator, 16, 16, 16, float> acc[2][2];
    float4 ra[2];
    uint4  rbh[2], rbl[2];

    for (int tile = blockIdx.x; tile < G1_NT; tile += gridDim.x) {
        const int block_row = tile * H1_ROWS;
        const int gr = block_row + arow;
        const bool avalid = (gr < N_NODES);
        const float4* xrow = (const float4*)(x + (size_t)gr * D_IN + acol);

#pragma unroll
        for (int mt = 0; mt < 2; mt++)
#pragma unroll
            for (int nt = 0; nt < 2; nt++) wmma::fill_fragment(acc[mt][nt], 0.0f);

        auto load_chunk = [&](int c) {
#pragma unroll
            for (int i = 0; i < 2; i++)
                ra[i] = avalid ? xrow[c * 8 + i] : make_float4(0.f, 0.f, 0.f, 0.f);
            rbh[0] = w1h4[(c * 32 + br0) * 16 + (bi0 & 15)];
            rbh[1] = w1h4[(c * 32 + br1) * 16 + (bi1 & 15)];
            rbl[0] = w1l4[(c * 32 + br0) * 16 + (bi0 & 15)];
            rbl[1] = w1l4[(c * 32 + br1) * 16 + (bi1 & 15)];
        };
        auto store_chunk = [&](int b) {
            char* base = smem + b * G1_BUF;
            __nv_bfloat16 (*Ah)[G1_LDA] = (__nv_bfloat16(*)[G1_LDA])(base);
            __nv_bfloat16 (*Al)[G1_LDA] = (__nv_bfloat16(*)[G1_LDA])(base + 5120);
            __nv_bfloat16 (*Bh)[G1_LDB] = (__nv_bfloat16(*)[G1_LDB])(base + 10240);
            __nv_bfloat16 (*Bl)[G1_LDB] = (__nv_bfloat16(*)[G1_LDB])(base + 18944);
#pragma unroll
            for (int i = 0; i < 2; i++) {
                __nv_bfloat16 hx, hy, hz, hw, lx, ly, lz, lw;
                cvt_split(ra[i].x, hx, lx); cvt_split(ra[i].y, hy, ly);
                cvt_split(ra[i].z, hz, lz); cvt_split(ra[i].w, hw, lw);
                int kc = acol + i * 4;
                __nv_bfloat162 h01(hx, hy), h23(hz, hw), l01(lx, ly), l23(lz, lw);
                *(uint2*)&Ah[arow][kc] =
                    make_uint2(*(uint32_t*)&h01, *(uint32_t*)&h23);
                *(uint2*)&Al[arow][kc] =
                    make_uint2(*(uint32_t*)&l01, *(uint32_t*)&l23);
            }
            *(uint4*)&Bh[br0][bc0] = rbh[0];
            *(uint4*)&Bh[br1][bc1] = rbh[1];
            *(uint4*)&Bl[br0][bc0] = rbl[0];
            *(uint4*)&Bl[br1][bc1] = rbl[1];
        };

        load_chunk(0);
        store_chunk(0);
        __syncthreads();

        for (int c = 0; c < D_IN / 32; c++) {
            if (c < D_IN / 32 - 1) load_chunk(c + 1);    // LDG issues early

            char* base = smem + (c & 1) * G1_BUF;
            __nv_bfloat16 (*Ah)[G1_LDA] = (__nv_bfloat16(*)[G1_LDA])(base);
            __nv_bfloat16 (*Al)[G1_LDA] = (__nv_bfloat16(*)[G1_LDA])(base + 5120);
            __nv_bfloat16 (*Bh)[G1_LDB] = (__nv_bfloat16(*)[G1_LDB])(base + 10240);
            __nv_bfloat16 (*Bl)[G1_LDB] = (__nv_bfloat16(*)[G1_LDB])(base + 18944);

#pragma unroll
            for (int ks = 0; ks < 32; ks += 16) {
                wmma::fragment<wmma::matrix_b, 16, 16, 16, __nv_bfloat16, wmma::row_major> fBh[2], fBl[2];
#pragma unroll
                for (int nt = 0; nt < 2; nt++) {
                    int col = warp_n * 32 + nt * 16;
                    wmma::load_matrix_sync(fBh[nt], &Bh[ks][col], G1_LDB);
                    wmma::load_matrix_sync(fBl[nt], &Bl[ks][col], G1_LDB);
                }
#pragma unroll
                for (int mt = 0; mt < 2; mt++) {
                    int row = warp_m * 32 + mt * 16;
                    wmma::fragment<wmma::matrix_a, 16, 16, 16, __nv_bfloat16, wmma::row_major> fAh, fAl;
                    wmma::load_matrix_sync(fAh, &Ah[row][ks], G1_LDA);
                    wmma::load_matrix_sync(fAl, &Al[row][ks], G1_LDA);
#pragma unroll
                    for (int nt = 0; nt < 2; nt++) {
                        wmma::mma_sync(acc[mt][nt], fAh, fBh[nt], acc[mt][nt]);
                        wmma::mma_sync(acc[mt][nt], fAh, fBl[nt], acc[mt][nt]);
                        wmma::mma_sync(acc[mt][nt], fAl, fBh[nt], acc[mt][nt]);
                    }
                }
            }
            if (c < D_IN / 32 - 1) store_chunk((c + 1) & 1);
            __syncthreads();
        }

        // Epilogue: stage 64x128 fp32 in smem, write g_h.
        float (*Cs)[G1_LDC] = (float(*)[G1_LDC])(smem);
#pragma unroll
        for (int mt = 0; mt < 2; mt++)
#pragma unroll
            for (int nt = 0; nt < 2; nt++)
                wmma::store_matrix_sync(&Cs[warp_m * 32 + mt * 16][warp_n * 32 + nt * 16],
                                        acc[mt][nt], G1_LDC, wmma::mem_row_major);
        __syncthreads();

        {
            int rr = t >> 2;                // 0..63
            int cq = (t & 3) * 32;
            int grow = block_row + rr;
            if (grow < N_NODES) {
                size_t base = (size_t)grow * D_HID + cq;
#pragma unroll
                for (int i = 0; i < 8; i++)
                    *(float4*)(g_h + base + i * 4) = *(float4*)&Cs[rr][cq + i * 4];
            }
        }
        __syncthreads();   // Cs region reused as tile buffers next iteration
    }
}

// ---------------------------------------------------------------------------
// Pull layer 1 (fully fused, pure store):
//   agg1[d] = dinv[d] * sum_j h[adj[d][j]] * dinv[adj[d][j]] + h[d]*dinv[d]^2
// One warp per dst node; lane owns float4 (128 floats). No atomics, no RMW.
// ---------------------------------------------------------------------------
__global__ __launch_bounds__(256) void k_pull1() {
    int wid  = threadIdx.x >> 5;
    int lane = threadIdx.x & 31;
    int d    = blockIdx.x * 8 + wid;           // grid = 12500 * 8 = 100000 exact
    const int n = g_cnt[d];
    const int* __restrict__ adj = g_adj + (size_t)d * ADJ_CAP;
    const int co = lane * 4;

    float4 a0 = make_float4(0.f, 0.f, 0.f, 0.f);
    float4 a1 = make_float4(0.f, 0.f, 0.f, 0.f);
    int j = 0;
    for (; j + 1 < n; j += 2) {
        int s0 = adj[j], s1 = adj[j + 1];
        float w0 = g_dinv[s0], w1 = g_dinv[s1];
        float4 v0 = *(const float4*)(g_h + (size_t)s0 * D_HID + co);
        float4 v1 = *(const float4*)(g_h + (size_t)s1 * D_HID + co);
        a0.x += v0.x * w0; a0.y += v0.y * w0; a0.z += v0.z * w0; a0.w += v0.w * w0;
        a1.x += v1.x * w1; a1.y += v1.y * w1; a1.z += v1.z * w1; a1.w += v1.w * w1;
    }
    if (j < n) {
        int s0 = adj[j];
        float w0 = g_dinv[s0];
        float4 v0 = *(const float4*)(g_h + (size_t)s0 * D_HID + co);
        a0.x += v0.x * w0; a0.y += v0.y * w0; a0.z += v0.z * w0; a0.w += v0.w * w0;
    }
    float wd  = g_dinv[d];
    float wd2 = wd * wd;
    float4 hd = *(const float4*)(g_h + (size_t)d * D_HID + co);
    *(float4*)(g_agg1 + (size_t)d * D_HID + co) =
        make_float4(wd * (a0.x + a1.x) + hd.x * wd2,
                    wd * (a0.y + a1.y) + hd.y * wd2,
                    wd * (a0.z + a1.z) + hd.z * wd2,
                    wd * (a0.w + a1.w) + hd.w * wd2);
}

// ---------------------------------------------------------------------------
// GEMM2 (wmma bf16 3-term split): h2 = relu(agg1+b1) @ W2  (K=128, N=64)
// 128x64 CTA tile, 8 warps (4x2). Epilogue: g_hs2 = h2*dinv,
// out = h2*dinv^2 + b2 (pull2 then accumulates into out).
// ---------------------------------------------------------------------------
#define G2_LDA 40
#define G2_LDB 72
#define G2_LDC 68

__global__ __launch_bounds__(256) void k_gemm2_w(const float* __restrict__ b1,
                                                 const float* __restrict__ W2,
                                                 const float* __restrict__ b2,
                                                 float* __restrict__ out) {
    __shared__ __align__(16) union {
        struct {
            __nv_bfloat16 Ah[128][G2_LDA];
            __nv_bfloat16 Al[128][G2_LDA];
            __nv_bfloat16 Bh[32][G2_LDB];
            __nv_bfloat16 Bl[32][G2_LDB];
        } tiles;
        float Cs[128][G2_LDC];
    } sm;

    const int t      = threadIdx.x;
    const int wid    = t >> 5;
    const int warp_m = wid >> 1;
    const int warp_n = wid & 1;
    const int block_row = blockIdx.x * 128;

    const int arow = t >> 1;
    const int akq  = (t & 1) * 16;
    const int gr   = block_row + arow;
    const bool avalid = (gr < N_NODES);

    const int bk = t >> 3;
    const int bq = (t & 7) * 8;

    wmma::fragment<wmma::accumulator, 16, 16, 16, float> acc[2][2];
#pragma unroll
    for (int mt = 0; mt < 2; mt++)
#pragma unroll
        for (int nt = 0; nt < 2; nt++) wmma::fill_fragment(acc[mt][nt], 0.0f);

    for (int c = 0; c < D_HID / 32; c++) {
        const int k0 = c * 32;
        {
            const float4* ap = (const float4*)(g_agg1 + (size_t)gr * D_HID + k0 + akq);
            const float4* bp = (const float4*)(b1 + k0 + akq);
#pragma unroll
            for (int i = 0; i < 4; i++) {
                float4 v  = avalid ? ap[i] : make_float4(0.f, 0.f, 0.f, 0.f);
                float4 bb = bp[i];
                v.x = fmaxf(v.x + bb.x, 0.f); v.y = fmaxf(v.y + bb.y, 0.f);
                v.z = fmaxf(v.z + bb.z, 0.f); v.w = fmaxf(v.w + bb.w, 0.f);
                __nv_bfloat16 hx, hy, hz, hw, lx, ly, lz, lw;
                cvt_split(v.x, hx, lx); cvt_split(v.y, hy, ly);
                cvt_split(v.z, hz, lz); cvt_split(v.w, hw, lw);
                int kc = akq + i * 4;
                *(__nv_bfloat162*)&sm.tiles.Ah[arow][kc]     = __nv_bfloat162(hx, hy);
                *(__nv_bfloat162*)&sm.tiles.Ah[arow][kc + 2] = __nv_bfloat162(hz, hw);
                *(__nv_bfloat162*)&sm.tiles.Al[arow][kc]     = __nv_bfloat162(lx, ly);
                *(__nv_bfloat162*)&sm.tiles.Al[arow][kc + 2] = __nv_bfloat162(lz, lw);
            }
        }
        {
            const float4* wp = (const float4*)(W2 + (size_t)(k0 + bk) * D_OUT + bq);
#pragma unroll
            for (int i = 0; i < 2; i++) {
                float4 v = wp[i];
                __nv_bfloat16 hx, hy, hz, hw, lx, ly, lz, lw;
                cvt_split(v.x, hx, lx); cvt_split(v.y, hy, ly);
                cvt_split(v.z, hz, lz); cvt_split(v.w, hw, lw);
                int nc = bq + i * 4;
                *(__nv_bfloat162*)&sm.tiles.Bh[bk][nc]     = __nv_bfloat162(hx, hy);
                *(__nv_bfloat162*)&sm.tiles.Bh[bk][nc + 2] = __nv_bfloat162(hz, hw);
                *(__nv_bfloat162*)&sm.tiles.Bl[bk][nc]     = __nv_bfloat162(lx, ly);
                *(__nv_bfloat162*)&sm.tiles.Bl[bk][nc + 2] = __nv_bfloat162(lz, lw);
            }
        }
        __syncthreads();

#pragma unroll
        for (int ks = 0; ks < 32; ks += 16) {
            wmma::fragment<wmma::matrix_b, 16, 16, 16, __nv_bfloat16, wmma::row_major> fBh[2], fBl[2];
#pragma unroll
            for (int nt = 0; nt < 2; nt++) {
                int col = warp_n * 32 + nt * 16;
                wmma::load_matrix_sync(fBh[nt], &sm.tiles.Bh[ks][col], G2_LDB);
                wmma::load_matrix_sync(fBl[nt], &sm.tiles.Bl[ks][col], G2_LDB);
            }
#pragma unroll
            for (int mt = 0; mt < 2; mt++) {
                int row = warp_m * 32 + mt * 16;
                wmma::fragment<wmma::matrix_a, 16, 16, 16, __nv_bfloat16, wmma::row_major> fAh, fAl;
                wmma::load_matrix_sync(fAh, &sm.tiles.Ah[row][ks], G2_LDA);
                wmma::load_matrix_sync(fAl, &sm.tiles.Al[row][ks], G2_LDA);
#pragma unroll
                for (int nt = 0; nt < 2; nt++) {
                    wmma::mma_sync(acc[mt][nt], fAh, fBh[nt], acc[mt][nt]);
                    wmma::mma_sync(acc[mt][nt], fAh, fBl[nt], acc[mt][nt]);
                    wmma::mma_sync(acc[mt][nt], fAl, fBh[nt], acc[mt][nt]);
                }
            }
        }
        __syncthreads();
    }

#pragma unroll
    for (int mt = 0; mt < 2; mt++)
#pragma unroll
        for (int nt = 0; nt < 2; nt++)
            wmma::store_matrix_sync(&sm.Cs[warp_m * 32 + mt * 16][warp_n * 32 + nt * 16],
                                    acc[mt][nt], G2_LDC, wmma::mem_row_major);
    __syncthreads();

    int rr = t >> 1;
    int ch = (t & 1) * 32;
    int grow = block_row + rr;
    if (grow < N_NODES) {
        float di  = g_dinv[grow];
        float di2 = di * di;
        size_t base = (size_t)grow * D_OUT + ch;
#pragma unroll
        for (int i = 0; i < 8; i++) {
            float4 v  = *(float4*)&sm.Cs[rr][ch + i * 4];
            float4 bb = *(const float4*)(b2 + ch + i * 4);
            *(float4*)(g_hs2 + base + i * 4) =
                make_float4(v.x * di, v.y * di, v.z * di, v.w * di);
            *(float4*)(out + base + i * 4) =
                make_float4(v.x * di2 + bb.x, v.y * di2 + bb.y,
                            v.z * di2 + bb.z, v.w * di2 + bb.w);
        }
    }
}

// ---------------------------------------------------------------------------
// Pull layer 2: out[d] += dinv[d] * sum hs2[adj[d][j]]  (hs2 pre-scaled)
// One warp per dst node; lane owns float2 (64 floats).
// ---------------------------------------------------------------------------
__global__ __launch_bounds__(256) void k_pull2(float* __restrict__ out) {
    int wid  = threadIdx.x >> 5;
    int lane = threadIdx.x & 31;
    int d    = blockIdx.x * 8 + wid;
    const int n = g_cnt[d];
    const int* __restrict__ adj = g_adj + (size_t)d * ADJ_CAP;
    const int co = lane * 2;

    float2 a0 = make_float2(0.f, 0.f);
    float2 a1 = make_float2(0.f, 0.f);
    int j = 0;
    for (; j + 1 < n; j += 2) {
        int s0 = adj[j], s1 = adj[j + 1];
        float2 v0 = *(const float2*)(g_hs2 + (size_t)s0 * D_OUT + co);
        float2 v1 = *(const float2*)(g_hs2 + (size_t)s1 * D_OUT + co);
        a0.x += v0.x; a0.y += v0.y;
        a1.x += v1.x; a1.y += v1.y;
    }
    if (j < n) {
        int s0 = adj[j];
        float2 v0 = *(const float2*)(g_hs2 + (size_t)s0 * D_OUT + co);
        a0.x += v0.x; a0.y += v0.y;
    }
    float w = g_dinv[d];
    float* p = out + (size_t)d * D_OUT + co;
    float2 cur = *(float2*)p;
    *(float2*)p = make_float2(cur.x + (a0.x + a1.x) * w,
                              cur.y + (a0.y + a1.y) * w);
}

// ---------------------------------------------------------------------------
// Launch sequence (graph-capturable: kernel launches only)
// ---------------------------------------------------------------------------
extern "C" void kernel_launch(void* const* d_in, const int* in_sizes, int n_in,
                              void* d_out, int out_size) {
    const float* x   = (const float*)d_in[0];
    const int*   ei  = (const int*)d_in[1];   // [2, E] int32
    const float* W1  = (const float*)d_in[2];
    const float* b1  = (const float*)d_in[3];
    const float* W2  = (const float*)d_in[4];
    const float* b2  = (const float*)d_in[5];
    float*       out = (float*)d_out;

    const int* src = ei;
    const int* dst = ei + N_EDGES;

    cudaFuncSetAttribute(k_gemm1_w, cudaFuncAttributeMaxDynamicSharedMemorySize, G1_SMEM);

    int smCount = 148;   // fallback; query actual (capture-safe host attribute read)
    cudaDeviceGetAttribute(&smCount, cudaDevAttrMultiProcessorCount, 0);
    int g1grid = 2 * smCount;

    // W1 -> bf16 hi/lo; adjacency buckets (also produces degree); dinv
    k_w1cvt   <<<(D_IN * D_HID + 255) / 256, 256>>>(W1);
    k_zero_cnt<<<(N_NODES + 255) / 256, 256>>>();
    k_fill    <<<(N_EDGES + 255) / 256, 256>>>(src, dst);
    k_dinv    <<<(N_NODES + 255) / 256, 256>>>();

    // layer 1 (persistent tensor GEMM + pull aggregation)
    k_gemm1_w<<<g1grid, 256, G1_SMEM>>>(x);
    k_pull1  <<<N_NODES / 8, 256>>>();

    // layer 2
    k_gemm2_w<<<(N_NODES + 127) / 128, 256>>>(b1, W2, b2, out);
    k_pull2  <<<N_NODES / 8, 256>>>(out);
}